// round 10
// baseline (speedup 1.0000x reference)
#include <cuda_runtime.h>
#include <cuda_bf16.h>
#include <cstdint>

// Problem constants
#define BATCH   2
#define SEQ     2048
#define DMODEL  1024
#define NHEADS  16
#define HDIM    64
#define TOKENS  (BATCH * SEQ)          // 4096
#define QKVDIM  (3 * DMODEL)           // 3072

// ---------------------------------------------------------------------------
// Scratch (no cudaMalloc allowed)
// ---------------------------------------------------------------------------
__device__ __nv_bfloat16 g_x_hi[(size_t)TOKENS * DMODEL];
__device__ __nv_bfloat16 g_x_lo[(size_t)TOKENS * DMODEL];
__device__ __nv_bfloat16 g_wqkv_hi[(size_t)QKVDIM * DMODEL];
__device__ __nv_bfloat16 g_wqkv_lo[(size_t)QKVDIM * DMODEL];
__device__ __nv_bfloat16 g_wout_hi[(size_t)DMODEL * DMODEL];
__device__ __nv_bfloat16 g_wout_lo[(size_t)DMODEL * DMODEL];
// head-major Q/K/V split: [which(3)][B*H][S][64]
__device__ __nv_bfloat16 g_hd_hi[(size_t)3 * TOKENS * DMODEL];
__device__ __nv_bfloat16 g_hd_lo[(size_t)3 * TOKENS * DMODEL];
// attention output, token-major [T][D], split
__device__ __nv_bfloat16 g_attn_hi[(size_t)TOKENS * DMODEL];
__device__ __nv_bfloat16 g_attn_lo[(size_t)TOKENS * DMODEL];

// ---------------------------------------------------------------------------
// Helpers (base ISA only — ptxas target is sm_103 without 'a')
// ---------------------------------------------------------------------------
__device__ __forceinline__ uint32_t smem_to_u32(const void* p) {
    uint32_t a;
    asm("{ .reg .u64 t; cvta.to.shared.u64 t, %1; cvt.u32.u64 %0, t; }" : "=r"(a) : "l"(p));
    return a;
}

#define CP_ASYNC16(dst, src) \
    asm volatile("cp.async.cg.shared.global [%0], [%1], 16;" :: "r"(dst), "l"(src) : "memory")
#define CP_COMMIT() asm volatile("cp.async.commit_group;" ::: "memory")
#define CP_WAIT(n)  asm volatile("cp.async.wait_group %0;" :: "n"(n) : "memory")

__device__ __forceinline__ void ldsm_x4(uint32_t addr, uint32_t& r0, uint32_t& r1,
                                        uint32_t& r2, uint32_t& r3) {
    asm volatile("ldmatrix.sync.aligned.m8n8.x4.shared.b16 {%0,%1,%2,%3}, [%4];"
                 : "=r"(r0), "=r"(r1), "=r"(r2), "=r"(r3) : "r"(addr));
}
__device__ __forceinline__ void ldsm_x4_t(uint32_t addr, uint32_t& r0, uint32_t& r1,
                                          uint32_t& r2, uint32_t& r3) {
    asm volatile("ldmatrix.sync.aligned.m8n8.x4.trans.shared.b16 {%0,%1,%2,%3}, [%4];"
                 : "=r"(r0), "=r"(r1), "=r"(r2), "=r"(r3) : "r"(addr));
}

__device__ __forceinline__ void mma_bf16(float* d, const uint32_t* a, const uint32_t* b) {
    asm volatile(
        "mma.sync.aligned.m16n8k16.row.col.f32.bf16.bf16.f32 "
        "{%0,%1,%2,%3}, {%4,%5,%6,%7}, {%8,%9}, {%0,%1,%2,%3};"
        : "+f"(d[0]), "+f"(d[1]), "+f"(d[2]), "+f"(d[3])
        : "r"(a[0]), "r"(a[1]), "r"(a[2]), "r"(a[3]), "r"(b[0]), "r"(b[1]));
}

__device__ __forceinline__ uint32_t pack_hi_bf16x2(float x, float y) {
    __nv_bfloat162 h = __floats2bfloat162_rn(x, y);
    return *(uint32_t*)&h;
}

// XOR swizzle for 64-byte rows (4 granules of 16B): conflict-free ldmatrix.
__device__ __forceinline__ uint32_t swz64(int row, int g) {
    return (uint32_t)(row * 64 + ((g ^ ((row >> 1) & 3)) << 4));
}
// XOR swizzle for 128-byte rows (8 granules of 16B): conflict-free ldmatrix.
__device__ __forceinline__ uint32_t swz128(int row, int g) {
    return (uint32_t)(row * 128 + ((g ^ (row & 7)) << 4));
}

// ---------------------------------------------------------------------------
// Unified split kernel: fp32 -> (hi bf16, lo bf16) for x, w_qkv, w_out
// ---------------------------------------------------------------------------
#define NX4 (TOKENS * DMODEL / 4)     // 1048576
#define NQ4 (QKVDIM * DMODEL / 4)     // 786432
#define NO4 (DMODEL * DMODEL / 4)     // 262144

__global__ void __launch_bounds__(256)
split_all_kernel(const float* __restrict__ x, const float* __restrict__ wq,
                 const float* __restrict__ wo,
                 __nv_bfloat16* __restrict__ xh, __nv_bfloat16* __restrict__ xl,
                 __nv_bfloat16* __restrict__ wqh, __nv_bfloat16* __restrict__ wql,
                 __nv_bfloat16* __restrict__ woh, __nv_bfloat16* __restrict__ wol)
{
    int i = blockIdx.x * blockDim.x + threadIdx.x;
    const float* in; __nv_bfloat16 *hi, *lo; int j;
    if (i < NX4)              { in = x;  hi = xh;  lo = xl;  j = i; }
    else if (i < NX4 + NQ4)   { in = wq; hi = wqh; lo = wql; j = i - NX4; }
    else if (i < NX4 + NQ4 + NO4) { in = wo; hi = woh; lo = wol; j = i - NX4 - NQ4; }
    else return;

    float4 v = ((const float4*)in)[j];
    __nv_bfloat16 h0 = __float2bfloat16_rn(v.x);
    __nv_bfloat16 h1 = __float2bfloat16_rn(v.y);
    __nv_bfloat16 h2 = __float2bfloat16_rn(v.z);
    __nv_bfloat16 h3 = __float2bfloat16_rn(v.w);
    __nv_bfloat16 l0 = __float2bfloat16_rn(v.x - __bfloat162float(h0));
    __nv_bfloat16 l1 = __float2bfloat16_rn(v.y - __bfloat162float(h1));
    __nv_bfloat16 l2 = __float2bfloat16_rn(v.z - __bfloat162float(h2));
    __nv_bfloat16 l3 = __float2bfloat16_rn(v.w - __bfloat162float(h3));
    ((__nv_bfloat162*)hi)[2 * j]     = __nv_bfloat162(h0, h1);
    ((__nv_bfloat162*)hi)[2 * j + 1] = __nv_bfloat162(h2, h3);
    ((__nv_bfloat162*)lo)[2 * j]     = __nv_bfloat162(l0, l1);
    ((__nv_bfloat162*)lo)[2 * j + 1] = __nv_bfloat162(l2, l3);
}

// ---------------------------------------------------------------------------
// GEMM mainloop (128x128 tile, BK=32, 3 stages, swizzled 64B rows, 8 warps).
// (R7 best-known configuration, unchanged.)
// ---------------------------------------------------------------------------
#define BK 32
#define NSTAGE 3
#define TILE_B (128 * 64)                  // 8192 bytes per 128x32 bf16 tile
#define STAGE_B (4 * TILE_B)               // 32768
#define GEMM_SMEM (NSTAGE * STAGE_B)       // 98304

__device__ __forceinline__ void gemm_load_stage(
    const __nv_bfloat16* __restrict__ Ahi, const __nv_bfloat16* __restrict__ Alo,
    const __nv_bfloat16* __restrict__ Bhi, const __nv_bfloat16* __restrict__ Blo,
    int K, int m0, int n0, int k0, uint32_t sbase, int tid)
{
#pragma unroll
    for (int t = 0; t < 8; t++) {
        int f    = tid + t * 256;
        int tile = f >> 9;
        int idx  = f & 511;
        int row  = idx >> 2;
        int g    = idx & 3;
        const __nv_bfloat16* src;
        if (tile == 0)      src = Ahi + (size_t)(m0 + row) * K + k0 + g * 8;
        else if (tile == 1) src = Alo + (size_t)(m0 + row) * K + k0 + g * 8;
        else if (tile == 2) src = Bhi + (size_t)(n0 + row) * K + k0 + g * 8;
        else                src = Blo + (size_t)(n0 + row) * K + k0 + g * 8;
        uint32_t dst = sbase + tile * TILE_B + swz64(row, g);
        CP_ASYNC16(dst, (const void*)src);
    }
}

#define GEMM_MAINLOOP(Ahi, Alo, Bhi, Blo, K) \
    float acc[4][4][4]; \
    _Pragma("unroll") for (int i = 0; i < 4; i++) \
    _Pragma("unroll") for (int j = 0; j < 4; j++) \
    _Pragma("unroll") for (int f = 0; f < 4; f++) acc[i][j][f] = 0.f; \
    gemm_load_stage(Ahi, Alo, Bhi, Blo, K, m0, n0, 0, smem_base, tid); \
    CP_COMMIT(); \
    gemm_load_stage(Ahi, Alo, Bhi, Blo, K, m0, n0, BK, smem_base + STAGE_B, tid); \
    CP_COMMIT(); \
    const int a_row_in_tile = wm * 64 + (lane & 15); \
    const int a_g           = lane >> 4; \
    const int b_row_in_tile = wn * 32 + ((lane >> 4) * 8) + (lane & 7); \
    const int b_g           = (lane >> 3) & 1; \
    const int nchunk = K / BK; \
    for (int i = 0; i < nchunk; i++) { \
        CP_WAIT(1); \
        __syncthreads(); \
        if (i + 2 < nchunk) \
            gemm_load_stage(Ahi, Alo, Bhi, Blo, K, m0, n0, (i + 2) * BK, \
                            smem_base + ((i + 2) % NSTAGE) * STAGE_B, tid); \
        CP_COMMIT(); \
        const uint32_t st = smem_base + (i % NSTAGE) * STAGE_B; \
        const uint32_t sAhi = st + 0 * TILE_B, sAlo = st + 1 * TILE_B; \
        const uint32_t sBhi = st + 2 * TILE_B, sBlo = st + 3 * TILE_B; \
        _Pragma("unroll") \
        for (int s = 0; s < 2; s++) { \
            uint32_t bh[4][2], bl[4][2]; \
            _Pragma("unroll") \
            for (int p = 0; p < 2; p++) { \
                uint32_t r0, r1, r2, r3; \
                ldsm_x4(sBhi + swz64(b_row_in_tile + p * 16, 2 * s + b_g), r0, r1, r2, r3); \
                bh[2 * p][0] = r0; bh[2 * p][1] = r1; bh[2 * p + 1][0] = r2; bh[2 * p + 1][1] = r3; \
                ldsm_x4(sBlo + swz64(b_row_in_tile + p * 16, 2 * s + b_g), r0, r1, r2, r3); \
                bl[2 * p][0] = r0; bl[2 * p][1] = r1; bl[2 * p + 1][0] = r2; bl[2 * p + 1][1] = r3; \
            } \
            _Pragma("unroll") \
            for (int mt = 0; mt < 4; mt++) { \
                uint32_t ah[4], al[4]; \
                ldsm_x4(sAhi + swz64(a_row_in_tile + mt * 16, 2 * s + a_g), \
                        ah[0], ah[1], ah[2], ah[3]); \
                ldsm_x4(sAlo + swz64(a_row_in_tile + mt * 16, 2 * s + a_g), \
                        al[0], al[1], al[2], al[3]); \
                _Pragma("unroll") \
                for (int nt = 0; nt < 4; nt++) { \
                    mma_bf16(acc[mt][nt], ah, bh[nt]); \
                    mma_bf16(acc[mt][nt], ah, bl[nt]); \
                    mma_bf16(acc[mt][nt], al, bh[nt]); \
                } \
            } \
        } \
    }

// ---------------------------------------------------------------------------
// QKV GEMM: writes head-major split q/k/v (Q pre-scaled by 1/8)
// ---------------------------------------------------------------------------
__global__ void __launch_bounds__(256, 2)
gemm_qkv(const __nv_bfloat16* __restrict__ Ahi, const __nv_bfloat16* __restrict__ Alo,
         const __nv_bfloat16* __restrict__ Bhi, const __nv_bfloat16* __restrict__ Blo,
         const float* __restrict__ bias,
         __nv_bfloat16* __restrict__ hd_hi, __nv_bfloat16* __restrict__ hd_lo)
{
    extern __shared__ __align__(128) unsigned char smem_raw[];
    const uint32_t smem_base = smem_to_u32(smem_raw);
    const int tid = threadIdx.x, wid = tid >> 5, lane = tid & 31;
    const int wm = wid >> 2, wn = wid & 3;
    const int m0 = blockIdx.y * 128, n0 = blockIdx.x * 128;
    const int K = DMODEL;

    GEMM_MAINLOOP(Ahi, Alo, Bhi, Blo, K)

    const int row_base = m0 + wm * 64 + (lane >> 2);
    const int col_base = n0 + wn * 32 + 2 * (lane & 3);
#pragma unroll
    for (int mt = 0; mt < 4; mt++) {
#pragma unroll
        for (int nt = 0; nt < 4; nt++) {
            int col = col_base + nt * 8;
            int which = col >> 10;
            int head  = (col >> 6) & 15;
            int dim   = col & 63;
            float b0 = bias[col], b1 = bias[col + 1];
            float sc = (which == 0) ? 0.125f : 1.0f;
#pragma unroll
            for (int rr = 0; rr < 2; rr++) {
                int row = row_base + mt * 16 + rr * 8;
                float v0 = (acc[mt][nt][2 * rr + 0] + b0) * sc;
                float v1 = (acc[mt][nt][2 * rr + 1] + b1) * sc;
                int bb = row >> 11, s = row & 2047;
                size_t addr = (((size_t)(which * (BATCH * NHEADS) + bb * NHEADS + head))
                               * SEQ + s) * HDIM + dim;
                uint32_t hp = pack_hi_bf16x2(v0, v1);
                __nv_bfloat162 hv = *(__nv_bfloat162*)&hp;
                float l0 = v0 - __bfloat162float(hv.x);
                float l1 = v1 - __bfloat162float(hv.y);
                *(uint32_t*)(hd_hi + addr) = hp;
                *(uint32_t*)(hd_lo + addr) = pack_hi_bf16x2(l0, l1);
            }
        }
    }
}

// ---------------------------------------------------------------------------
// Out-proj GEMM: fp32 output + bias
// ---------------------------------------------------------------------------
__global__ void __launch_bounds__(256, 2)
gemm_splitbf16(const __nv_bfloat16* __restrict__ Ahi, const __nv_bfloat16* __restrict__ Alo,
               const __nv_bfloat16* __restrict__ Bhi, const __nv_bfloat16* __restrict__ Blo,
               const float* __restrict__ bias, float* __restrict__ C,
               int M, int N, int K)
{
    extern __shared__ __align__(128) unsigned char smem_raw[];
    const uint32_t smem_base = smem_to_u32(smem_raw);
    const int tid = threadIdx.x, wid = tid >> 5, lane = tid & 31;
    const int wm = wid >> 2, wn = wid & 3;
    const int m0 = blockIdx.y * 128, n0 = blockIdx.x * 128;

    GEMM_MAINLOOP(Ahi, Alo, Bhi, Blo, K)

    const int row_base = m0 + wm * 64 + (lane >> 2);
    const int col_base = n0 + wn * 32 + 2 * (lane & 3);
#pragma unroll
    for (int mt = 0; mt < 4; mt++) {
#pragma unroll
        for (int nt = 0; nt < 4; nt++) {
            int col = col_base + nt * 8;
            float b0 = bias[col], b1 = bias[col + 1];
            int r0 = row_base + mt * 16;
            *(float2*)(C + (size_t)r0 * N + col) =
                make_float2(acc[mt][nt][0] + b0, acc[mt][nt][1] + b1);
            *(float2*)(C + (size_t)(r0 + 8) * N + col) =
                make_float2(acc[mt][nt][2] + b0, acc[mt][nt][3] + b1);
        }
    }
}

// ---------------------------------------------------------------------------
// Flash attention with mma.sync, split-bf16 precision.
// CTA: 64 q-rows x one (b,h), 128 threads (4 warps x 16 rows).
// Q fragments loaded gmem->regs (no Q smem). KV swizzled 128B rows.
// 2-stage KV pipeline, smem 64KB -> 3 CTAs/SM (12 warps/SM).
// ---------------------------------------------------------------------------
#define ATHREADS   128
#define KV_TILE_B  (64 * 128)              // 8192 (swizzled, no padding)
#define KV_STAGE_B (4 * KV_TILE_B)         // 32768
#define ATTN_SMEM  (2 * KV_STAGE_B)        // 65536

__device__ __forceinline__ void attn_load_kv(
    const __nv_bfloat16* Kh, const __nv_bfloat16* Kl,
    const __nv_bfloat16* Vh, const __nv_bfloat16* Vl,
    int kc, uint32_t stg, int tid)
{
#pragma unroll
    for (int t = 0; t < 16; t++) {
        int f = tid + t * ATHREADS;        // 0..2047
        int tile = f >> 9;
        int idx  = f & 511;
        int row  = idx >> 3;
        int g    = idx & 7;
        const __nv_bfloat16* src;
        if (tile == 0)      src = Kh + (size_t)(kc + row) * HDIM + g * 8;
        else if (tile == 1) src = Kl + (size_t)(kc + row) * HDIM + g * 8;
        else if (tile == 2) src = Vh + (size_t)(kc + row) * HDIM + g * 8;
        else                src = Vl + (size_t)(kc + row) * HDIM + g * 8;
        uint32_t dst = stg + tile * KV_TILE_B + swz128(row, g);
        CP_ASYNC16(dst, (const void*)src);
    }
}

__global__ void __launch_bounds__(ATHREADS, 3)
attn_mma(const __nv_bfloat16* __restrict__ hd_hi, const __nv_bfloat16* __restrict__ hd_lo,
         __nv_bfloat16* __restrict__ out_hi, __nv_bfloat16* __restrict__ out_lo)
{
    extern __shared__ __align__(128) unsigned char smem_raw[];
    const uint32_t smem_base = smem_to_u32(smem_raw);
    const int tid  = threadIdx.x;
    const int w    = tid >> 5;             // 0..3
    const int lane = tid & 31;
    const int bh   = blockIdx.y;
    const int q0   = (gridDim.x - 1 - blockIdx.x) * 64;   // longest CTAs first
    const int b    = bh >> 4;
    const int h    = bh & 15;

    const size_t headelems = (size_t)SEQ * HDIM;
    const __nv_bfloat16* Qh = hd_hi + (size_t)bh * headelems;
    const __nv_bfloat16* Ql = hd_lo + (size_t)bh * headelems;
    const __nv_bfloat16* Kh = hd_hi + (size_t)(BATCH * NHEADS + bh) * headelems;
    const __nv_bfloat16* Kl = hd_lo + (size_t)(BATCH * NHEADS + bh) * headelems;
    const __nv_bfloat16* Vh = hd_hi + (size_t)(2 * BATCH * NHEADS + bh) * headelems;
    const __nv_bfloat16* Vl = hd_lo + (size_t)(2 * BATCH * NHEADS + bh) * headelems;

    const uint32_t kvbase = smem_base;

    // ---- Prologue: KV chunks 0 and 1 into smem ----
    attn_load_kv(Kh, Kl, Vh, Vl, 0, kvbase, tid);
    CP_COMMIT();
    attn_load_kv(Kh, Kl, Vh, Vl, 64, kvbase + KV_STAGE_B, tid);
    CP_COMMIT();

    // ---- Q fragments: gmem -> registers (A-frag lane mapping, exact) ----
    uint32_t qh[4][4], ql[4][4];
    {
        const int r  = q0 + 16 * w + (lane >> 2);
        const int c  = 2 * (lane & 3);
        const __nv_bfloat16* q0p = Qh + (size_t)r * HDIM + c;
        const __nv_bfloat16* q1p = Ql + (size_t)r * HDIM + c;
#pragma unroll
        for (int s = 0; s < 4; s++) {
            qh[s][0] = *(const uint32_t*)(q0p + 16 * s);
            qh[s][1] = *(const uint32_t*)(q0p + 8 * HDIM + 16 * s);
            qh[s][2] = *(const uint32_t*)(q0p + 16 * s + 8);
            qh[s][3] = *(const uint32_t*)(q0p + 8 * HDIM + 16 * s + 8);
            ql[s][0] = *(const uint32_t*)(q1p + 16 * s);
            ql[s][1] = *(const uint32_t*)(q1p + 8 * HDIM + 16 * s);
            ql[s][2] = *(const uint32_t*)(q1p + 16 * s + 8);
            ql[s][3] = *(const uint32_t*)(q1p + 8 * HDIM + 16 * s + 8);
        }
    }

    const int nch = q0 / 64 + 1;

    float o[8][4];
#pragma unroll
    for (int j = 0; j < 8; j++)
#pragma unroll
        for (int e = 0; e < 4; e++) o[j][e] = 0.f;
    float m0r = -1e30f, m1r = -1e30f, l0r = 0.f, l1r = 0.f;

    const int g0 = q0 + 16 * w + (lane >> 2);
    const int g1 = g0 + 8;
    const int cb = 2 * (lane & 3);
    const int krow  = ((lane >> 4) * 8) + (lane & 7);
    const int kg    = (lane >> 3) & 1;    // K-side granule parity
    const int vrow  = lane & 15;          // V trans row within 16-block
    const int vg    = lane >> 4;          // V-side granule parity

    for (int c = 0; c < nch; c++) {
        CP_WAIT(1);
        __syncthreads();

        const int kc = c * 64;
        const bool active = (kc <= q0 + 16 * w + 15);
        if (active) {
            const uint32_t stg = kvbase + (c & 1) * KV_STAGE_B;
            const uint32_t sKh = stg, sKl = stg + KV_TILE_B;
            const uint32_t sVh = stg + 2 * KV_TILE_B, sVl = stg + 3 * KV_TILE_B;

            // ---- S = Q K^T (3-pass split) ----
            float sfr[8][4];
#pragma unroll
            for (int j = 0; j < 8; j++)
#pragma unroll
                for (int e = 0; e < 4; e++) sfr[j][e] = 0.f;

#pragma unroll
            for (int s = 0; s < 4; s++) {
#pragma unroll
                for (int p = 0; p < 4; p++) {
                    uint32_t h0, h1, h2, h3, lo0, lo1, lo2, lo3;
                    ldsm_x4(sKh + swz128(16 * p + krow, 2 * s + kg), h0, h1, h2, h3);
                    ldsm_x4(sKl + swz128(16 * p + krow, 2 * s + kg), lo0, lo1, lo2, lo3);
                    uint32_t bh0[2] = {h0, h1}, bh1[2] = {h2, h3};
                    uint32_t bl0[2] = {lo0, lo1}, bl1[2] = {lo2, lo3};
                    mma_bf16(sfr[2 * p],     qh[s], bh0);
                    mma_bf16(sfr[2 * p],     qh[s], bl0);
                    mma_bf16(sfr[2 * p],     ql[s], bh0);
                    mma_bf16(sfr[2 * p + 1], qh[s], bh1);
                    mma_bf16(sfr[2 * p + 1], qh[s], bl1);
                    mma_bf16(sfr[2 * p + 1], ql[s], bh1);
                }
            }

            // ---- causal mask ----
            if (kc + 63 > g0) {
#pragma unroll
                for (int j = 0; j < 8; j++) {
                    int col = kc + 8 * j + cb;
                    if (col     > g0) sfr[j][0] = -1e30f;
                    if (col + 1 > g0) sfr[j][1] = -1e30f;
                    if (col     > g1) sfr[j][2] = -1e30f;
                    if (col + 1 > g1) sfr[j][3] = -1e30f;
                }
            }

            // ---- online softmax (exp in place) ----
            float mx0 = -1e30f, mx1 = -1e30f;
#pragma unroll
            for (int j = 0; j < 8; j++) {
                mx0 = fmaxf(mx0, fmaxf(sfr[j][0], sfr[j][1]));
                mx1 = fmaxf(mx1, fmaxf(sfr[j][2], sfr[j][3]));
            }
            mx0 = fmaxf(mx0, __shfl_xor_sync(0xffffffffu, mx0, 1));
            mx0 = fmaxf(mx0, __shfl_xor_sync(0xffffffffu, mx0, 2));
            mx1 = fmaxf(mx1, __shfl_xor_sync(0xffffffffu, mx1, 1));
            mx1 = fmaxf(mx1, __shfl_xor_sync(0xffffffffu, mx1, 2));

            float mn0 = fmaxf(m0r, mx0), mn1 = fmaxf(m1r, mx1);
            float cr0 = __expf(m0r - mn0), cr1 = __expf(m1r - mn1);
            float sum0 = 0.f, sum1 = 0.f;
#pragma unroll
            for (int j = 0; j < 8; j++) {
                sfr[j][0] = __expf(sfr[j][0] - mn0);
                sfr[j][1] = __expf(sfr[j][1] - mn0);
                sfr[j][2] = __expf(sfr[j][2] - mn1);
                sfr[j][3] = __expf(sfr[j][3] - mn1);
                sum0 += sfr[j][0] + sfr[j][1];
                sum1 += sfr[j][2] + sfr[j][3];
            }
            sum0 += __shfl_xor_sync(0xffffffffu, sum0, 1);
            sum0 += __shfl_xor_sync(0xffffffffu, sum0, 2);
            sum1 += __shfl_xor_sync(0xffffffffu, sum1, 1);
            sum1 += __shfl_xor_sync(0xffffffffu, sum1, 2);

            l0r = l0r * cr0 + sum0;
            l1r = l1r * cr1 + sum1;
            m0r = mn0; m1r = mn1;
#pragma unroll
            for (int j = 0; j < 8; j++) {
                o[j][0] *= cr0; o[j][1] *= cr0;
                o[j][2] *= cr1; o[j][3] *= cr1;
            }

            // ---- O += P V (fused pack + 3-pass split) ----
#pragma unroll
            for (int t = 0; t < 4; t++) {
                uint32_t ph[4], pl[4];
                {
                    const float* s0p = sfr[2 * t];
                    const float* s1p = sfr[2 * t + 1];
                    float v[8] = {s0p[0], s0p[1], s0p[2], s0p[3],
                                  s1p[0], s1p[1], s1p[2], s1p[3]};
#pragma unroll
                    for (int q = 0; q < 4; q++) {
                        uint32_t hp = pack_hi_bf16x2(v[2 * q], v[2 * q + 1]);
                        __nv_bfloat162 hv = *(__nv_bfloat162*)&hp;
                        float lo0 = v[2 * q]     - __bfloat162float(hv.x);
                        float lo1 = v[2 * q + 1] - __bfloat162float(hv.y);
                        ph[q] = hp;
                        pl[q] = pack_hi_bf16x2(lo0, lo1);
                    }
                }
#pragma unroll
                for (int d = 0; d < 4; d++) {
                    uint32_t v0, v1, v2, v3, w0, w1, w2, w3;
                    ldsm_x4_t(sVh + swz128(16 * t + vrow, 2 * d + vg), v0, v1, v2, v3);
                    ldsm_x4_t(sVl + swz128(16 * t + vrow, 2 * d + vg), w0, w1, w2, w3);
                    uint32_t bh0[2] = {v0, v1}, bh1[2] = {v2, v3};
                    uint32_t bl0[2] = {w0, w1}, bl1[2] = {w2, w3};
                    mma_bf16(o[2 * d],     ph, bh0);
                    mma_bf16(o[2 * d],     ph, bl0);
                    mma_bf16(o[2 * d],     pl, bh0);
                    mma_bf16(o[2 * d + 1], ph, bh1);
                    mma_bf16(o[2 * d + 1], ph, bl1);
                    mma_bf16(o[2 * d + 1], pl, bh1);
                }
            }
        }
        __syncthreads();   // all warps done reading stage c&1
        if (c + 2 < nch)
            attn_load_kv(Kh, Kl, Vh, Vl, (c + 2) * 64,
                         kvbase + (c & 1) * KV_STAGE_B, tid);
        CP_COMMIT();
    }
    CP_WAIT(0);   // drain speculative prologue prefetch before exit

    // ---- epilogue: normalize, split, store ----
    const float i0 = 1.0f / l0r, i1 = 1.0f / l1r;
    const size_t base0 = ((size_t)(b * SEQ + g0)) * DMODEL + h * HDIM + cb;
    const size_t base1 = ((size_t)(b * SEQ + g1)) * DMODEL + h * HDIM + cb;
#pragma unroll
    for (int j = 0; j < 8; j++) {
        float x0 = o[j][0] * i0, x1 = o[j][1] * i0;
        float y0 = o[j][2] * i1, y1 = o[j][3] * i1;
        uint32_t hp0 = pack_hi_bf16x2(x0, x1);
        __nv_bfloat162 hv0 = *(__nv_bfloat162*)&hp0;
        uint32_t lp0 = pack_hi_bf16x2(x0 - __bfloat162float(hv0.x),
                                      x1 - __bfloat162float(hv0.y));
        uint32_t hp1 = pack_hi_bf16x2(y0, y1);
        __nv_bfloat162 hv1 = *(__nv_bfloat162*)&hp1;
        uint32_t lp1 = pack_hi_bf16x2(y0 - __bfloat162float(hv1.x),
                                      y1 - __bfloat162float(hv1.y));
        *(uint32_t*)(out_hi + base0 + 8 * j) = hp0;
        *(uint32_t*)(out_lo + base0 + 8 * j) = lp0;
        *(uint32_t*)(out_hi + base1 + 8 * j) = hp1;
        *(uint32_t*)(out_lo + base1 + 8 * j) = lp1;
    }
}

// ---------------------------------------------------------------------------
// Launch
// ---------------------------------------------------------------------------
extern "C" void kernel_launch(void* const* d_in, const int* in_sizes, int n_in,
                              void* d_out, int out_size)
{
    const float* x     = (const float*)d_in[0];
    const float* w_qkv = (const float*)d_in[1];
    const float* b_qkv = (const float*)d_in[2];
    const float* w_out = (const float*)d_in[3];
    const float* b_out = (const float*)d_in[4];
    float* out = (float*)d_out;

    __nv_bfloat16 *x_hi, *x_lo, *wq_hi, *wq_lo, *wo_hi, *wo_lo;
    __nv_bfloat16 *hd_hi, *hd_lo, *at_hi, *at_lo;
    cudaGetSymbolAddress((void**)&x_hi,  g_x_hi);
    cudaGetSymbolAddress((void**)&x_lo,  g_x_lo);
    cudaGetSymbolAddress((void**)&wq_hi, g_wqkv_hi);
    cudaGetSymbolAddress((void**)&wq_lo, g_wqkv_lo);
    cudaGetSymbolAddress((void**)&wo_hi, g_wout_hi);
    cudaGetSymbolAddress((void**)&wo_lo, g_wout_lo);
    cudaGetSymbolAddress((void**)&hd_hi, g_hd_hi);
    cudaGetSymbolAddress((void**)&hd_lo, g_hd_lo);
    cudaGetSymbolAddress((void**)&at_hi, g_attn_hi);
    cudaGetSymbolAddress((void**)&at_lo, g_attn_lo);

    cudaFuncSetAttribute(gemm_qkv,
                         cudaFuncAttributeMaxDynamicSharedMemorySize, GEMM_SMEM);
    cudaFuncSetAttribute(gemm_splitbf16,
                         cudaFuncAttributeMaxDynamicSharedMemorySize, GEMM_SMEM);
    cudaFuncSetAttribute(attn_mma,
                         cudaFuncAttributeMaxDynamicSharedMemorySize, ATTN_SMEM);

    // Unified splits (1 launch)
    {
        int total = NX4 + NQ4 + NO4;
        split_all_kernel<<<(total + 255) / 256, 256>>>(
            x, w_qkv, w_out, x_hi, x_lo, wq_hi, wq_lo, wo_hi, wo_lo);
    }

    // 1) QKV projection -> head-major split q/k/v
    {
        dim3 grid(QKVDIM / 128, TOKENS / 128);
        gemm_qkv<<<grid, 256, GEMM_SMEM>>>(x_hi, x_lo, wq_hi, wq_lo, b_qkv, hd_hi, hd_lo);
    }

    // 2) Flash attention (64-row CTAs, 3 CTAs/SM) -> split attn output
    {
        dim3 grid(SEQ / 64, BATCH * NHEADS);
        attn_mma<<<grid, ATHREADS, ATTN_SMEM>>>(hd_hi, hd_lo, at_hi, at_lo);
    }

    // 3) Output projection
    {
        dim3 grid(DMODEL / 128, TOKENS / 128);
        gemm_splitbf16<<<grid, 256, GEMM_SMEM>>>(
            at_hi, at_lo, wo_hi, wo_lo, b_out, out, TOKENS, DMODEL, DMODEL);
    }
}

// round 11
// speedup vs baseline: 1.1506x; 1.1506x over previous
#include <cuda_runtime.h>
#include <cuda_fp16.h>
#include <cstdint>

// Problem constants
#define BATCH   2
#define SEQ     2048
#define DMODEL  1024
#define NHEADS  16
#define HDIM    64
#define TOKENS  (BATCH * SEQ)          // 4096
#define QKVDIM  (3 * DMODEL)           // 3072

// ---------------------------------------------------------------------------
// Scratch (no cudaMalloc allowed) — fp16 split pairs
// ---------------------------------------------------------------------------
__device__ __half g_x_hi[(size_t)TOKENS * DMODEL];
__device__ __half g_x_lo[(size_t)TOKENS * DMODEL];
__device__ __half g_wqkv_hi[(size_t)QKVDIM * DMODEL];
__device__ __half g_wqkv_lo[(size_t)QKVDIM * DMODEL];
__device__ __half g_wout_hi[(size_t)DMODEL * DMODEL];
__device__ __half g_wout_lo[(size_t)DMODEL * DMODEL];
// head-major Q/K/V split: [which(3)][B*H][S][64]
__device__ __half g_hd_hi[(size_t)3 * TOKENS * DMODEL];
__device__ __half g_hd_lo[(size_t)3 * TOKENS * DMODEL];
// attention output, token-major [T][D], split
__device__ __half g_attn_hi[(size_t)TOKENS * DMODEL];
__device__ __half g_attn_lo[(size_t)TOKENS * DMODEL];

// ---------------------------------------------------------------------------
// Helpers (base ISA only — ptxas target is sm_103 without 'a')
// ---------------------------------------------------------------------------
__device__ __forceinline__ uint32_t smem_to_u32(const void* p) {
    uint32_t a;
    asm("{ .reg .u64 t; cvta.to.shared.u64 t, %1; cvt.u32.u64 %0, t; }" : "=r"(a) : "l"(p));
    return a;
}

#define CP_ASYNC16(dst, src) \
    asm volatile("cp.async.cg.shared.global [%0], [%1], 16;" :: "r"(dst), "l"(src) : "memory")
#define CP_COMMIT() asm volatile("cp.async.commit_group;" ::: "memory")
#define CP_WAIT(n)  asm volatile("cp.async.wait_group %0;" :: "n"(n) : "memory")

__device__ __forceinline__ void ldsm_x4(uint32_t addr, uint32_t& r0, uint32_t& r1,
                                        uint32_t& r2, uint32_t& r3) {
    asm volatile("ldmatrix.sync.aligned.m8n8.x4.shared.b16 {%0,%1,%2,%3}, [%4];"
                 : "=r"(r0), "=r"(r1), "=r"(r2), "=r"(r3) : "r"(addr));
}
__device__ __forceinline__ void ldsm_x4_t(uint32_t addr, uint32_t& r0, uint32_t& r1,
                                          uint32_t& r2, uint32_t& r3) {
    asm volatile("ldmatrix.sync.aligned.m8n8.x4.trans.shared.b16 {%0,%1,%2,%3}, [%4];"
                 : "=r"(r0), "=r"(r1), "=r"(r2), "=r"(r3) : "r"(addr));
}

__device__ __forceinline__ void mma_f16(float* d, const uint32_t* a, const uint32_t* b) {
    asm volatile(
        "mma.sync.aligned.m16n8k16.row.col.f32.f16.f16.f32 "
        "{%0,%1,%2,%3}, {%4,%5,%6,%7}, {%8,%9}, {%0,%1,%2,%3};"
        : "+f"(d[0]), "+f"(d[1]), "+f"(d[2]), "+f"(d[3])
        : "r"(a[0]), "r"(a[1]), "r"(a[2]), "r"(a[3]), "r"(b[0]), "r"(b[1]));
}

__device__ __forceinline__ uint32_t pack_h2(float x, float y) {
    __half2 h = __floats2half2_rn(x, y);
    return *(uint32_t*)&h;
}

// XOR swizzle for 64-byte rows (4 granules of 16B): conflict-free ldmatrix.
__device__ __forceinline__ uint32_t swz64(int row, int g) {
    return (uint32_t)(row * 64 + ((g ^ ((row >> 1) & 3)) << 4));
}
// XOR swizzle for 128-byte rows (8 granules of 16B): conflict-free ldmatrix.
__device__ __forceinline__ uint32_t swz128(int row, int g) {
    return (uint32_t)(row * 128 + ((g ^ (row & 7)) << 4));
}

// ---------------------------------------------------------------------------
// Unified split kernel: fp32 -> (hi fp16, lo fp16) for x, w_qkv, w_out
// ---------------------------------------------------------------------------
#define NX4 (TOKENS * DMODEL / 4)     // 1048576
#define NQ4 (QKVDIM * DMODEL / 4)     // 786432
#define NO4 (DMODEL * DMODEL / 4)     // 262144

__global__ void __launch_bounds__(256)
split_all_kernel(const float* __restrict__ x, const float* __restrict__ wq,
                 const float* __restrict__ wo,
                 __half* __restrict__ xh, __half* __restrict__ xl,
                 __half* __restrict__ wqh, __half* __restrict__ wql,
                 __half* __restrict__ woh, __half* __restrict__ wol)
{
    int i = blockIdx.x * blockDim.x + threadIdx.x;
    const float* in; __half *hi, *lo; int j;
    if (i < NX4)              { in = x;  hi = xh;  lo = xl;  j = i; }
    else if (i < NX4 + NQ4)   { in = wq; hi = wqh; lo = wql; j = i - NX4; }
    else if (i < NX4 + NQ4 + NO4) { in = wo; hi = woh; lo = wol; j = i - NX4 - NQ4; }
    else return;

    float4 v = ((const float4*)in)[j];
    __half h0 = __float2half_rn(v.x);
    __half h1 = __float2half_rn(v.y);
    __half h2 = __float2half_rn(v.z);
    __half h3 = __float2half_rn(v.w);
    __half l0 = __float2half_rn(v.x - __half2float(h0));
    __half l1 = __float2half_rn(v.y - __half2float(h1));
    __half l2 = __float2half_rn(v.z - __half2float(h2));
    __half l3 = __float2half_rn(v.w - __half2float(h3));
    ((__half2*)hi)[2 * j]     = __half2(h0, h1);
    ((__half2*)hi)[2 * j + 1] = __half2(h2, h3);
    ((__half2*)lo)[2 * j]     = __half2(l0, l1);
    ((__half2*)lo)[2 * j + 1] = __half2(l2, l3);
}

// ---------------------------------------------------------------------------
// GEMM mainloop (128x128 tile, BK=32, 3 stages, swizzled 64B rows, 8 warps).
// Split-fp16, 3 passes (error ~1e-7).
// ---------------------------------------------------------------------------
#define BK 32
#define NSTAGE 3
#define TILE_B (128 * 64)                  // 8192 bytes per 128x32 fp16 tile
#define STAGE_B (4 * TILE_B)               // 32768
#define GEMM_SMEM (NSTAGE * STAGE_B)       // 98304

__device__ __forceinline__ void gemm_load_stage(
    const __half* __restrict__ Ahi, const __half* __restrict__ Alo,
    const __half* __restrict__ Bhi, const __half* __restrict__ Blo,
    int K, int m0, int n0, int k0, uint32_t sbase, int tid)
{
#pragma unroll
    for (int t = 0; t < 8; t++) {
        int f    = tid + t * 256;
        int tile = f >> 9;
        int idx  = f & 511;
        int row  = idx >> 2;
        int g    = idx & 3;
        const __half* src;
        if (tile == 0)      src = Ahi + (size_t)(m0 + row) * K + k0 + g * 8;
        else if (tile == 1) src = Alo + (size_t)(m0 + row) * K + k0 + g * 8;
        else if (tile == 2) src = Bhi + (size_t)(n0 + row) * K + k0 + g * 8;
        else                src = Blo + (size_t)(n0 + row) * K + k0 + g * 8;
        uint32_t dst = sbase + tile * TILE_B + swz64(row, g);
        CP_ASYNC16(dst, (const void*)src);
    }
}

#define GEMM_MAINLOOP(Ahi, Alo, Bhi, Blo, K) \
    float acc[4][4][4]; \
    _Pragma("unroll") for (int i = 0; i < 4; i++) \
    _Pragma("unroll") for (int j = 0; j < 4; j++) \
    _Pragma("unroll") for (int f = 0; f < 4; f++) acc[i][j][f] = 0.f; \
    gemm_load_stage(Ahi, Alo, Bhi, Blo, K, m0, n0, 0, smem_base, tid); \
    CP_COMMIT(); \
    gemm_load_stage(Ahi, Alo, Bhi, Blo, K, m0, n0, BK, smem_base + STAGE_B, tid); \
    CP_COMMIT(); \
    const int a_row_in_tile = wm * 64 + (lane & 15); \
    const int a_g           = lane >> 4; \
    const int b_row_in_tile = wn * 32 + ((lane >> 4) * 8) + (lane & 7); \
    const int b_g           = (lane >> 3) & 1; \
    const int nchunk = K / BK; \
    for (int i = 0; i < nchunk; i++) { \
        CP_WAIT(1); \
        __syncthreads(); \
        if (i + 2 < nchunk) \
            gemm_load_stage(Ahi, Alo, Bhi, Blo, K, m0, n0, (i + 2) * BK, \
                            smem_base + ((i + 2) % NSTAGE) * STAGE_B, tid); \
        CP_COMMIT(); \
        const uint32_t st = smem_base + (i % NSTAGE) * STAGE_B; \
        const uint32_t sAhi = st + 0 * TILE_B, sAlo = st + 1 * TILE_B; \
        const uint32_t sBhi = st + 2 * TILE_B, sBlo = st + 3 * TILE_B; \
        _Pragma("unroll") \
        for (int s = 0; s < 2; s++) { \
            uint32_t bh[4][2], bl[4][2]; \
            _Pragma("unroll") \
            for (int p = 0; p < 2; p++) { \
                uint32_t r0, r1, r2, r3; \
                ldsm_x4(sBhi + swz64(b_row_in_tile + p * 16, 2 * s + b_g), r0, r1, r2, r3); \
                bh[2 * p][0] = r0; bh[2 * p][1] = r1; bh[2 * p + 1][0] = r2; bh[2 * p + 1][1] = r3; \
                ldsm_x4(sBlo + swz64(b_row_in_tile + p * 16, 2 * s + b_g), r0, r1, r2, r3); \
                bl[2 * p][0] = r0; bl[2 * p][1] = r1; bl[2 * p + 1][0] = r2; bl[2 * p + 1][1] = r3; \
            } \
            _Pragma("unroll") \
            for (int mt = 0; mt < 4; mt++) { \
                uint32_t ah[4], al[4]; \
                ldsm_x4(sAhi + swz64(a_row_in_tile + mt * 16, 2 * s + a_g), \
                        ah[0], ah[1], ah[2], ah[3]); \
                ldsm_x4(sAlo + swz64(a_row_in_tile + mt * 16, 2 * s + a_g), \
                        al[0], al[1], al[2], al[3]); \
                _Pragma("unroll") \
                for (int nt = 0; nt < 4; nt++) { \
                    mma_f16(acc[mt][nt], ah, bh[nt]); \
                    mma_f16(acc[mt][nt], ah, bl[nt]); \
                    mma_f16(acc[mt][nt], al, bh[nt]); \
                } \
            } \
        } \
    }

// ---------------------------------------------------------------------------
// QKV GEMM: writes head-major split q/k/v (no Q pre-scale; applied in attn)
// ---------------------------------------------------------------------------
__global__ void __launch_bounds__(256, 2)
gemm_qkv(const __half* __restrict__ Ahi, const __half* __restrict__ Alo,
         const __half* __restrict__ Bhi, const __half* __restrict__ Blo,
         const float* __restrict__ bias,
         __half* __restrict__ hd_hi, __half* __restrict__ hd_lo)
{
    extern __shared__ __align__(128) unsigned char smem_raw[];
    const uint32_t smem_base = smem_to_u32(smem_raw);
    const int tid = threadIdx.x, wid = tid >> 5, lane = tid & 31;
    const int wm = wid >> 2, wn = wid & 3;
    const int m0 = blockIdx.y * 128, n0 = blockIdx.x * 128;
    const int K = DMODEL;

    GEMM_MAINLOOP(Ahi, Alo, Bhi, Blo, K)

    const int row_base = m0 + wm * 64 + (lane >> 2);
    const int col_base = n0 + wn * 32 + 2 * (lane & 3);
#pragma unroll
    for (int mt = 0; mt < 4; mt++) {
#pragma unroll
        for (int nt = 0; nt < 4; nt++) {
            int col = col_base + nt * 8;
            int which = col >> 10;
            int head  = (col >> 6) & 15;
            int dim   = col & 63;
            float b0 = bias[col], b1 = bias[col + 1];
#pragma unroll
            for (int rr = 0; rr < 2; rr++) {
                int row = row_base + mt * 16 + rr * 8;
                float v0 = acc[mt][nt][2 * rr + 0] + b0;
                float v1 = acc[mt][nt][2 * rr + 1] + b1;
                int bb = row >> 11, s = row & 2047;
                size_t addr = (((size_t)(which * (BATCH * NHEADS) + bb * NHEADS + head))
                               * SEQ + s) * HDIM + dim;
                uint32_t hp = pack_h2(v0, v1);
                __half2 hv = *(__half2*)&hp;
                float l0 = v0 - __half2float(hv.x);
                float l1 = v1 - __half2float(hv.y);
                *(uint32_t*)(hd_hi + addr) = hp;
                *(uint32_t*)(hd_lo + addr) = pack_h2(l0, l1);
            }
        }
    }
}

// ---------------------------------------------------------------------------
// Out-proj GEMM: fp32 output + bias
// ---------------------------------------------------------------------------
__global__ void __launch_bounds__(256, 2)
gemm_splitf16(const __half* __restrict__ Ahi, const __half* __restrict__ Alo,
              const __half* __restrict__ Bhi, const __half* __restrict__ Blo,
              const float* __restrict__ bias, float* __restrict__ C,
              int M, int N, int K)
{
    extern __shared__ __align__(128) unsigned char smem_raw[];
    const uint32_t smem_base = smem_to_u32(smem_raw);
    const int tid = threadIdx.x, wid = tid >> 5, lane = tid & 31;
    const int wm = wid >> 2, wn = wid & 3;
    const int m0 = blockIdx.y * 128, n0 = blockIdx.x * 128;

    GEMM_MAINLOOP(Ahi, Alo, Bhi, Blo, K)

    const int row_base = m0 + wm * 64 + (lane >> 2);
    const int col_base = n0 + wn * 32 + 2 * (lane & 3);
#pragma unroll
    for (int mt = 0; mt < 4; mt++) {
#pragma unroll
        for (int nt = 0; nt < 4; nt++) {
            int col = col_base + nt * 8;
            float b0 = bias[col], b1 = bias[col + 1];
            int r0 = row_base + mt * 16;
            *(float2*)(C + (size_t)r0 * N + col) =
                make_float2(acc[mt][nt][0] + b0, acc[mt][nt][1] + b1);
            *(float2*)(C + (size_t)(r0 + 8) * N + col) =
                make_float2(acc[mt][nt][2] + b0, acc[mt][nt][3] + b1);
        }
    }
}

// ---------------------------------------------------------------------------
// Flash attention, fp16 mixed precision:
//   QK: (Qhi + Qlo) x Khi      (2 passes; K whole-fp16, err ~5e-5 on scores)
//   PV: (Phi + Plo) x Vhi      (2 passes; V whole-fp16, err ~3e-4 on O)
// CTA: 64 q-rows x one (b,h), 128 threads. KV stage = Kh+Vh only (16KB).
// ---------------------------------------------------------------------------
#define ATHREADS   128
#define KV_TILE_B  (64 * 128)              // 8192 (swizzled)
#define KV_STAGE_B (2 * KV_TILE_B)         // 16384 (Kh + Vh only)
#define ATTN_SMEM  (2 * KV_STAGE_B)        // 32768

__device__ __forceinline__ void attn_load_kv(
    const __half* Kh, const __half* Vh, int kc, uint32_t stg, int tid)
{
#pragma unroll
    for (int t = 0; t < 8; t++) {
        int f = tid + t * ATHREADS;        // 0..1023
        int tile = f >> 9;
        int idx  = f & 511;
        int row  = idx >> 3;
        int g    = idx & 7;
        const __half* src = (tile ? Vh : Kh) + (size_t)(kc + row) * HDIM + g * 8;
        uint32_t dst = stg + tile * KV_TILE_B + swz128(row, g);
        CP_ASYNC16(dst, (const void*)src);
    }
}

__global__ void __launch_bounds__(ATHREADS, 3)
attn_mma(const __half* __restrict__ hd_hi, const __half* __restrict__ hd_lo,
         __half* __restrict__ out_hi, __half* __restrict__ out_lo)
{
    extern __shared__ __align__(128) unsigned char smem_raw[];
    const uint32_t smem_base = smem_to_u32(smem_raw);
    const int tid  = threadIdx.x;
    const int w    = tid >> 5;             // 0..3
    const int lane = tid & 31;
    const int bh   = blockIdx.y;
    const int q0   = (gridDim.x - 1 - blockIdx.x) * 64;   // longest CTAs first
    const int b    = bh >> 4;
    const int h    = bh & 15;

    const size_t headelems = (size_t)SEQ * HDIM;
    const __half* Qh = hd_hi + (size_t)bh * headelems;
    const __half* Ql = hd_lo + (size_t)bh * headelems;
    const __half* Kh = hd_hi + (size_t)(BATCH * NHEADS + bh) * headelems;
    const __half* Vh = hd_hi + (size_t)(2 * BATCH * NHEADS + bh) * headelems;

    const uint32_t kvbase = smem_base;

    // ---- Prologue: KV chunks 0 and 1 ----
    attn_load_kv(Kh, Vh, 0, kvbase, tid);
    CP_COMMIT();
    attn_load_kv(Kh, Vh, 64, kvbase + KV_STAGE_B, tid);
    CP_COMMIT();

    // ---- Q fragments: gmem -> registers (A-frag lane mapping) ----
    uint32_t qh[4][4], ql[4][4];
    {
        const int r  = q0 + 16 * w + (lane >> 2);
        const int c  = 2 * (lane & 3);
        const __half* q0p = Qh + (size_t)r * HDIM + c;
        const __half* q1p = Ql + (size_t)r * HDIM + c;
#pragma unroll
        for (int s = 0; s < 4; s++) {
            qh[s][0] = *(const uint32_t*)(q0p + 16 * s);
            qh[s][1] = *(const uint32_t*)(q0p + 8 * HDIM + 16 * s);
            qh[s][2] = *(const uint32_t*)(q0p + 16 * s + 8);
            qh[s][3] = *(const uint32_t*)(q0p + 8 * HDIM + 16 * s + 8);
            ql[s][0] = *(const uint32_t*)(q1p + 16 * s);
            ql[s][1] = *(const uint32_t*)(q1p + 8 * HDIM + 16 * s);
            ql[s][2] = *(const uint32_t*)(q1p + 16 * s + 8);
            ql[s][3] = *(const uint32_t*)(q1p + 8 * HDIM + 16 * s + 8);
        }
    }

    const int nch = q0 / 64 + 1;

    float o[8][4];
#pragma unroll
    for (int j = 0; j < 8; j++)
#pragma unroll
        for (int e = 0; e < 4; e++) o[j][e] = 0.f;
    float m0r = -1e30f, m1r = -1e30f, l0r = 0.f, l1r = 0.f;

    const int g0 = q0 + 16 * w + (lane >> 2);
    const int g1 = g0 + 8;
    const int cb = 2 * (lane & 3);
    const int krow  = ((lane >> 4) * 8) + (lane & 7);
    const int kg    = (lane >> 3) & 1;
    const int vrow  = lane & 15;
    const int vg    = lane >> 4;

    for (int c = 0; c < nch; c++) {
        CP_WAIT(1);
        __syncthreads();

        const int kc = c * 64;
        const bool active = (kc <= q0 + 16 * w + 15);
        if (active) {
            const uint32_t stg = kvbase + (c & 1) * KV_STAGE_B;
            const uint32_t sKh = stg;
            const uint32_t sVh = stg + KV_TILE_B;

            // ---- S = (Qhi + Qlo) Khi^T  (2 passes) ----
            float sfr[8][4];
#pragma unroll
            for (int j = 0; j < 8; j++)
#pragma unroll
                for (int e = 0; e < 4; e++) sfr[j][e] = 0.f;

#pragma unroll
            for (int s = 0; s < 4; s++) {
#pragma unroll
                for (int p = 0; p < 4; p++) {
                    uint32_t h0, h1, h2, h3;
                    ldsm_x4(sKh + swz128(16 * p + krow, 2 * s + kg), h0, h1, h2, h3);
                    uint32_t bh0[2] = {h0, h1}, bh1[2] = {h2, h3};
                    mma_f16(sfr[2 * p],     qh[s], bh0);
                    mma_f16(sfr[2 * p],     ql[s], bh0);
                    mma_f16(sfr[2 * p + 1], qh[s], bh1);
                    mma_f16(sfr[2 * p + 1], ql[s], bh1);
                }
            }

            // ---- scale + causal mask ----
#pragma unroll
            for (int j = 0; j < 8; j++) {
                sfr[j][0] *= 0.125f; sfr[j][1] *= 0.125f;
                sfr[j][2] *= 0.125f; sfr[j][3] *= 0.125f;
            }
            if (kc + 63 > g0) {
#pragma unroll
                for (int j = 0; j < 8; j++) {
                    int col = kc + 8 * j + cb;
                    if (col     > g0) sfr[j][0] = -1e30f;
                    if (col + 1 > g0) sfr[j][1] = -1e30f;
                    if (col     > g1) sfr[j][2] = -1e30f;
                    if (col + 1 > g1) sfr[j][3] = -1e30f;
                }
            }

            // ---- online softmax (exp in place) ----
            float mx0 = -1e30f, mx1 = -1e30f;
#pragma unroll
            for (int j = 0; j < 8; j++) {
                mx0 = fmaxf(mx0, fmaxf(sfr[j][0], sfr[j][1]));
                mx1 = fmaxf(mx1, fmaxf(sfr[j][2], sfr[j][3]));
            }
            mx0 = fmaxf(mx0, __shfl_xor_sync(0xffffffffu, mx0, 1));
            mx0 = fmaxf(mx0, __shfl_xor_sync(0xffffffffu, mx0, 2));
            mx1 = fmaxf(mx1, __shfl_xor_sync(0xffffffffu, mx1, 1));
            mx1 = fmaxf(mx1, __shfl_xor_sync(0xffffffffu, mx1, 2));

            float mn0 = fmaxf(m0r, mx0), mn1 = fmaxf(m1r, mx1);
            float cr0 = __expf(m0r - mn0), cr1 = __expf(m1r - mn1);
            float sum0 = 0.f, sum1 = 0.f;
#pragma unroll
            for (int j = 0; j < 8; j++) {
                sfr[j][0] = __expf(sfr[j][0] - mn0);
                sfr[j][1] = __expf(sfr[j][1] - mn0);
                sfr[j][2] = __expf(sfr[j][2] - mn1);
                sfr[j][3] = __expf(sfr[j][3] - mn1);
                sum0 += sfr[j][0] + sfr[j][1];
                sum1 += sfr[j][2] + sfr[j][3];
            }
            sum0 += __shfl_xor_sync(0xffffffffu, sum0, 1);
            sum0 += __shfl_xor_sync(0xffffffffu, sum0, 2);
            sum1 += __shfl_xor_sync(0xffffffffu, sum1, 1);
            sum1 += __shfl_xor_sync(0xffffffffu, sum1, 2);

            l0r = l0r * cr0 + sum0;
            l1r = l1r * cr1 + sum1;
            m0r = mn0; m1r = mn1;
#pragma unroll
            for (int j = 0; j < 8; j++) {
                o[j][0] *= cr0; o[j][1] *= cr0;
                o[j][2] *= cr1; o[j][3] *= cr1;
            }

            // ---- O += (Phi + Plo) Vhi  (fused pack, 2 passes) ----
#pragma unroll
            for (int t = 0; t < 4; t++) {
                uint32_t ph[4], pl[4];
                {
                    const float* s0p = sfr[2 * t];
                    const float* s1p = sfr[2 * t + 1];
                    float v[8] = {s0p[0], s0p[1], s0p[2], s0p[3],
                                  s1p[0], s1p[1], s1p[2], s1p[3]};
#pragma unroll
                    for (int q = 0; q < 4; q++) {
                        uint32_t hp = pack_h2(v[2 * q], v[2 * q + 1]);
                        __half2 hv = *(__half2*)&hp;
                        float lo0 = v[2 * q]     - __half2float(hv.x);
                        float lo1 = v[2 * q + 1] - __half2float(hv.y);
                        ph[q] = hp;
                        pl[q] = pack_h2(lo0, lo1);
                    }
                }
#pragma unroll
                for (int d = 0; d < 4; d++) {
                    uint32_t v0, v1, v2, v3;
                    ldsm_x4_t(sVh + swz128(16 * t + vrow, 2 * d + vg), v0, v1, v2, v3);
                    uint32_t bh0[2] = {v0, v1}, bh1[2] = {v2, v3};
                    mma_f16(o[2 * d],     ph, bh0);
                    mma_f16(o[2 * d],     pl, bh0);
                    mma_f16(o[2 * d + 1], ph, bh1);
                    mma_f16(o[2 * d + 1], pl, bh1);
                }
            }
        }
        __syncthreads();   // all warps done reading stage c&1
        if (c + 2 < nch)
            attn_load_kv(Kh, Vh, (c + 2) * 64, kvbase + (c & 1) * KV_STAGE_B, tid);
        CP_COMMIT();
    }
    CP_WAIT(0);   // drain speculative prologue prefetch

    // ---- epilogue: normalize, split, store ----
    const float i0 = 1.0f / l0r, i1 = 1.0f / l1r;
    const size_t base0 = ((size_t)(b * SEQ + g0)) * DMODEL + h * HDIM + cb;
    const size_t base1 = ((size_t)(b * SEQ + g1)) * DMODEL + h * HDIM + cb;
#pragma unroll
    for (int j = 0; j < 8; j++) {
        float x0 = o[j][0] * i0, x1 = o[j][1] * i0;
        float y0 = o[j][2] * i1, y1 = o[j][3] * i1;
        uint32_t hp0 = pack_h2(x0, x1);
        __half2 hv0 = *(__half2*)&hp0;
        uint32_t lp0 = pack_h2(x0 - __half2float(hv0.x), x1 - __half2float(hv0.y));
        uint32_t hp1 = pack_h2(y0, y1);
        __half2 hv1 = *(__half2*)&hp1;
        uint32_t lp1 = pack_h2(y0 - __half2float(hv1.x), y1 - __half2float(hv1.y));
        *(uint32_t*)(out_hi + base0 + 8 * j) = hp0;
        *(uint32_t*)(out_lo + base0 + 8 * j) = lp0;
        *(uint32_t*)(out_hi + base1 + 8 * j) = hp1;
        *(uint32_t*)(out_lo + base1 + 8 * j) = lp1;
    }
}

// ---------------------------------------------------------------------------
// Launch
// ---------------------------------------------------------------------------
extern "C" void kernel_launch(void* const* d_in, const int* in_sizes, int n_in,
                              void* d_out, int out_size)
{
    const float* x     = (const float*)d_in[0];
    const float* w_qkv = (const float*)d_in[1];
    const float* b_qkv = (const float*)d_in[2];
    const float* w_out = (const float*)d_in[3];
    const float* b_out = (const float*)d_in[4];
    float* out = (float*)d_out;

    __half *x_hi, *x_lo, *wq_hi, *wq_lo, *wo_hi, *wo_lo;
    __half *hd_hi, *hd_lo, *at_hi, *at_lo;
    cudaGetSymbolAddress((void**)&x_hi,  g_x_hi);
    cudaGetSymbolAddress((void**)&x_lo,  g_x_lo);
    cudaGetSymbolAddress((void**)&wq_hi, g_wqkv_hi);
    cudaGetSymbolAddress((void**)&wq_lo, g_wqkv_lo);
    cudaGetSymbolAddress((void**)&wo_hi, g_wout_hi);
    cudaGetSymbolAddress((void**)&wo_lo, g_wout_lo);
    cudaGetSymbolAddress((void**)&hd_hi, g_hd_hi);
    cudaGetSymbolAddress((void**)&hd_lo, g_hd_lo);
    cudaGetSymbolAddress((void**)&at_hi, g_attn_hi);
    cudaGetSymbolAddress((void**)&at_lo, g_attn_lo);

    cudaFuncSetAttribute(gemm_qkv,
                         cudaFuncAttributeMaxDynamicSharedMemorySize, GEMM_SMEM);
    cudaFuncSetAttribute(gemm_splitf16,
                         cudaFuncAttributeMaxDynamicSharedMemorySize, GEMM_SMEM);
    cudaFuncSetAttribute(attn_mma,
                         cudaFuncAttributeMaxDynamicSharedMemorySize, ATTN_SMEM);

    // Unified splits (1 launch)
    {
        int total = NX4 + NQ4 + NO4;
        split_all_kernel<<<(total + 255) / 256, 256>>>(
            x, w_qkv, w_out, x_hi, x_lo, wq_hi, wq_lo, wo_hi, wo_lo);
    }

    // 1) QKV projection -> head-major split q/k/v
    {
        dim3 grid(QKVDIM / 128, TOKENS / 128);
        gemm_qkv<<<grid, 256, GEMM_SMEM>>>(x_hi, x_lo, wq_hi, wq_lo, b_qkv, hd_hi, hd_lo);
    }

    // 2) Flash attention (fp16, 2-pass QK + 2-pass PV) -> split attn output
    {
        dim3 grid(SEQ / 64, BATCH * NHEADS);
        attn_mma<<<grid, ATHREADS, ATTN_SMEM>>>(hd_hi, hd_lo, at_hi, at_lo);
    }

    // 3) Output projection
    {
        dim3 grid(DMODEL / 128, TOKENS / 128);
        gemm_splitf16<<<grid, 256, GEMM_SMEM>>>(
            at_hi, at_lo, wo_hi, wo_lo, b_out, out, TOKENS, DMODEL, DMODEL);
    }
}

// round 12
// speedup vs baseline: 1.4301x; 1.2429x over previous
#include <cuda_runtime.h>
#include <cuda_fp16.h>
#include <cstdint>

// Problem constants
#define BATCH   2
#define SEQ     2048
#define DMODEL  1024
#define NHEADS  16
#define HDIM    64
#define TOKENS  (BATCH * SEQ)          // 4096
#define QKVDIM  (3 * DMODEL)           // 3072

// ---------------------------------------------------------------------------
// Scratch (no cudaMalloc allowed) — fp16
// ---------------------------------------------------------------------------
__device__ __half g_x_hi[(size_t)TOKENS * DMODEL];
__device__ __half g_x_lo[(size_t)TOKENS * DMODEL];
__device__ __half g_wqkv_hi[(size_t)QKVDIM * DMODEL];
__device__ __half g_wout_hi[(size_t)DMODEL * DMODEL];
// head-major Q/K/V split: [which(3)][B*H][S][64]; lo used only for Q
__device__ __half g_hd_hi[(size_t)3 * TOKENS * DMODEL];
__device__ __half g_hd_lo[(size_t)3 * TOKENS * DMODEL];
// attention output, token-major [T][D], split
__device__ __half g_attn_hi[(size_t)TOKENS * DMODEL];
__device__ __half g_attn_lo[(size_t)TOKENS * DMODEL];

// ---------------------------------------------------------------------------
// Helpers (base ISA only — ptxas target is sm_103 without 'a')
// ---------------------------------------------------------------------------
__device__ __forceinline__ uint32_t smem_to_u32(const void* p) {
    uint32_t a;
    asm("{ .reg .u64 t; cvta.to.shared.u64 t, %1; cvt.u32.u64 %0, t; }" : "=r"(a) : "l"(p));
    return a;
}

#define CP_ASYNC16(dst, src) \
    asm volatile("cp.async.cg.shared.global [%0], [%1], 16;" :: "r"(dst), "l"(src) : "memory")
#define CP_COMMIT() asm volatile("cp.async.commit_group;" ::: "memory")
#define CP_WAIT(n)  asm volatile("cp.async.wait_group %0;" :: "n"(n) : "memory")

__device__ __forceinline__ void ldsm_x4(uint32_t addr, uint32_t& r0, uint32_t& r1,
                                        uint32_t& r2, uint32_t& r3) {
    asm volatile("ldmatrix.sync.aligned.m8n8.x4.shared.b16 {%0,%1,%2,%3}, [%4];"
                 : "=r"(r0), "=r"(r1), "=r"(r2), "=r"(r3) : "r"(addr));
}
__device__ __forceinline__ void ldsm_x4_t(uint32_t addr, uint32_t& r0, uint32_t& r1,
                                          uint32_t& r2, uint32_t& r3) {
    asm volatile("ldmatrix.sync.aligned.m8n8.x4.trans.shared.b16 {%0,%1,%2,%3}, [%4];"
                 : "=r"(r0), "=r"(r1), "=r"(r2), "=r"(r3) : "r"(addr));
}

__device__ __forceinline__ void mma_f16(float* d, const uint32_t* a, const uint32_t* b) {
    asm volatile(
        "mma.sync.aligned.m16n8k16.row.col.f32.f16.f16.f32 "
        "{%0,%1,%2,%3}, {%4,%5,%6,%7}, {%8,%9}, {%0,%1,%2,%3};"
        : "+f"(d[0]), "+f"(d[1]), "+f"(d[2]), "+f"(d[3])
        : "r"(a[0]), "r"(a[1]), "r"(a[2]), "r"(a[3]), "r"(b[0]), "r"(b[1]));
}

__device__ __forceinline__ uint32_t pack_h2(float x, float y) {
    __half2 h = __floats2half2_rn(x, y);
    return *(uint32_t*)&h;
}

// XOR swizzles: conflict-free ldmatrix on 64B / 128B rows.
__device__ __forceinline__ uint32_t swz64(int row, int g) {
    return (uint32_t)(row * 64 + ((g ^ ((row >> 1) & 3)) << 4));
}
__device__ __forceinline__ uint32_t swz128(int row, int g) {
    return (uint32_t)(row * 128 + ((g ^ (row & 7)) << 4));
}

// ---------------------------------------------------------------------------
// Unified split kernel: x -> hi+lo; weights -> hi only
// ---------------------------------------------------------------------------
#define NX4 (TOKENS * DMODEL / 4)     // 1048576
#define NQ4 (QKVDIM * DMODEL / 4)     // 786432
#define NO4 (DMODEL * DMODEL / 4)     // 262144

__global__ void __launch_bounds__(256)
split_all_kernel(const float* __restrict__ x, const float* __restrict__ wq,
                 const float* __restrict__ wo,
                 __half* __restrict__ xh, __half* __restrict__ xl,
                 __half* __restrict__ wqh, __half* __restrict__ woh)
{
    int i = blockIdx.x * blockDim.x + threadIdx.x;
    const float* in; __half *hi, *lo; int j; bool want_lo;
    if (i < NX4)              { in = x;  hi = xh;  lo = xl; j = i; want_lo = true; }
    else if (i < NX4 + NQ4)   { in = wq; hi = wqh; lo = 0;  j = i - NX4; want_lo = false; }
    else if (i < NX4 + NQ4 + NO4) { in = wo; hi = woh; lo = 0; j = i - NX4 - NQ4; want_lo = false; }
    else return;

    float4 v = ((const float4*)in)[j];
    __half h0 = __float2half_rn(v.x);
    __half h1 = __float2half_rn(v.y);
    __half h2 = __float2half_rn(v.z);
    __half h3 = __float2half_rn(v.w);
    ((__half2*)hi)[2 * j]     = __half2(h0, h1);
    ((__half2*)hi)[2 * j + 1] = __half2(h2, h3);
    if (want_lo) {
        __half l0 = __float2half_rn(v.x - __half2float(h0));
        __half l1 = __float2half_rn(v.y - __half2float(h1));
        __half l2 = __float2half_rn(v.z - __half2float(h2));
        __half l3 = __float2half_rn(v.w - __half2float(h3));
        ((__half2*)lo)[2 * j]     = __half2(l0, l1);
        ((__half2*)lo)[2 * j + 1] = __half2(l2, l3);
    }
}

// ---------------------------------------------------------------------------
// GEMM mainloop: C = (Ahi + Alo) x Bhi^T  (2-pass; weights whole-fp16).
// 128x128 tile, BK=32, 3 stages of 3 tiles (24KB), 8 warps, 2 CTAs/SM.
// ---------------------------------------------------------------------------
#define BK 32
#define NSTAGE 3
#define TILE_B (128 * 64)                  // 8192 bytes per 128x32 fp16 tile
#define STAGE_B (3 * TILE_B)               // 24576 (Ahi, Alo, Bhi)
#define GEMM_SMEM (NSTAGE * STAGE_B)       // 73728

__device__ __forceinline__ void gemm_load_stage(
    const __half* __restrict__ Ahi, const __half* __restrict__ Alo,
    const __half* __restrict__ Bhi,
    int K, int m0, int n0, int k0, uint32_t sbase, int tid)
{
#pragma unroll
    for (int t = 0; t < 6; t++) {
        int f    = tid + t * 256;          // 0..1535
        int tile = f >> 9;                 // 0..2
        int idx  = f & 511;
        int row  = idx >> 2;
        int g    = idx & 3;
        const __half* src;
        if (tile == 0)      src = Ahi + (size_t)(m0 + row) * K + k0 + g * 8;
        else if (tile == 1) src = Alo + (size_t)(m0 + row) * K + k0 + g * 8;
        else                src = Bhi + (size_t)(n0 + row) * K + k0 + g * 8;
        uint32_t dst = sbase + tile * TILE_B + swz64(row, g);
        CP_ASYNC16(dst, (const void*)src);
    }
}

#define GEMM_MAINLOOP(Ahi, Alo, Bhi, K) \
    float acc[4][4][4]; \
    _Pragma("unroll") for (int i = 0; i < 4; i++) \
    _Pragma("unroll") for (int j = 0; j < 4; j++) \
    _Pragma("unroll") for (int f = 0; f < 4; f++) acc[i][j][f] = 0.f; \
    gemm_load_stage(Ahi, Alo, Bhi, K, m0, n0, 0, smem_base, tid); \
    CP_COMMIT(); \
    gemm_load_stage(Ahi, Alo, Bhi, K, m0, n0, BK, smem_base + STAGE_B, tid); \
    CP_COMMIT(); \
    const int a_row_in_tile = wm * 64 + (lane & 15); \
    const int a_g           = lane >> 4; \
    const int b_row_in_tile = wn * 32 + ((lane >> 4) * 8) + (lane & 7); \
    const int b_g           = (lane >> 3) & 1; \
    const int nchunk = K / BK; \
    for (int i = 0; i < nchunk; i++) { \
        CP_WAIT(1); \
        __syncthreads(); \
        if (i + 2 < nchunk) \
            gemm_load_stage(Ahi, Alo, Bhi, K, m0, n0, (i + 2) * BK, \
                            smem_base + ((i + 2) % NSTAGE) * STAGE_B, tid); \
        CP_COMMIT(); \
        const uint32_t st = smem_base + (i % NSTAGE) * STAGE_B; \
        const uint32_t sAhi = st + 0 * TILE_B, sAlo = st + 1 * TILE_B; \
        const uint32_t sBhi = st + 2 * TILE_B; \
        _Pragma("unroll") \
        for (int s = 0; s < 2; s++) { \
            uint32_t bh[4][2]; \
            _Pragma("unroll") \
            for (int p = 0; p < 2; p++) { \
                uint32_t r0, r1, r2, r3; \
                ldsm_x4(sBhi + swz64(b_row_in_tile + p * 16, 2 * s + b_g), r0, r1, r2, r3); \
                bh[2 * p][0] = r0; bh[2 * p][1] = r1; bh[2 * p + 1][0] = r2; bh[2 * p + 1][1] = r3; \
            } \
            _Pragma("unroll") \
            for (int mt = 0; mt < 4; mt++) { \
                uint32_t ah[4], al[4]; \
                ldsm_x4(sAhi + swz64(a_row_in_tile + mt * 16, 2 * s + a_g), \
                        ah[0], ah[1], ah[2], ah[3]); \
                ldsm_x4(sAlo + swz64(a_row_in_tile + mt * 16, 2 * s + a_g), \
                        al[0], al[1], al[2], al[3]); \
                _Pragma("unroll") \
                for (int nt = 0; nt < 4; nt++) { \
                    mma_f16(acc[mt][nt], ah, bh[nt]); \
                    mma_f16(acc[mt][nt], al, bh[nt]); \
                } \
            } \
        } \
    }

// ---------------------------------------------------------------------------
// QKV GEMM: writes head-major q/k/v (hi; lo only for Q)
// ---------------------------------------------------------------------------
__global__ void __launch_bounds__(256, 2)
gemm_qkv(const __half* __restrict__ Ahi, const __half* __restrict__ Alo,
         const __half* __restrict__ Bhi,
         const float* __restrict__ bias,
         __half* __restrict__ hd_hi, __half* __restrict__ hd_lo)
{
    extern __shared__ __align__(128) unsigned char smem_raw[];
    const uint32_t smem_base = smem_to_u32(smem_raw);
    const int tid = threadIdx.x, wid = tid >> 5, lane = tid & 31;
    const int wm = wid >> 2, wn = wid & 3;
    const int m0 = blockIdx.y * 128, n0 = blockIdx.x * 128;
    const int K = DMODEL;

    GEMM_MAINLOOP(Ahi, Alo, Bhi, K)

    const int row_base = m0 + wm * 64 + (lane >> 2);
    const int col_base = n0 + wn * 32 + 2 * (lane & 3);
#pragma unroll
    for (int mt = 0; mt < 4; mt++) {
#pragma unroll
        for (int nt = 0; nt < 4; nt++) {
            int col = col_base + nt * 8;
            int which = col >> 10;
            int head  = (col >> 6) & 15;
            int dim   = col & 63;
            float b0 = bias[col], b1 = bias[col + 1];
#pragma unroll
            for (int rr = 0; rr < 2; rr++) {
                int row = row_base + mt * 16 + rr * 8;
                float v0 = acc[mt][nt][2 * rr + 0] + b0;
                float v1 = acc[mt][nt][2 * rr + 1] + b1;
                int bb = row >> 11, s = row & 2047;
                size_t addr = (((size_t)(which * (BATCH * NHEADS) + bb * NHEADS + head))
                               * SEQ + s) * HDIM + dim;
                uint32_t hp = pack_h2(v0, v1);
                *(uint32_t*)(hd_hi + addr) = hp;
                if (which == 0) {   // lo needed only for Q
                    __half2 hv = *(__half2*)&hp;
                    float l0 = v0 - __half2float(hv.x);
                    float l1 = v1 - __half2float(hv.y);
                    *(uint32_t*)(hd_lo + addr) = pack_h2(l0, l1);
                }
            }
        }
    }
}

// ---------------------------------------------------------------------------
// Out-proj GEMM: fp32 output + bias
// ---------------------------------------------------------------------------
__global__ void __launch_bounds__(256, 2)
gemm_splitf16(const __half* __restrict__ Ahi, const __half* __restrict__ Alo,
              const __half* __restrict__ Bhi,
              const float* __restrict__ bias, float* __restrict__ C,
              int M, int N, int K)
{
    extern __shared__ __align__(128) unsigned char smem_raw[];
    const uint32_t smem_base = smem_to_u32(smem_raw);
    const int tid = threadIdx.x, wid = tid >> 5, lane = tid & 31;
    const int wm = wid >> 2, wn = wid & 3;
    const int m0 = blockIdx.y * 128, n0 = blockIdx.x * 128;

    GEMM_MAINLOOP(Ahi, Alo, Bhi, K)

    const int row_base = m0 + wm * 64 + (lane >> 2);
    const int col_base = n0 + wn * 32 + 2 * (lane & 3);
#pragma unroll
    for (int mt = 0; mt < 4; mt++) {
#pragma unroll
        for (int nt = 0; nt < 4; nt++) {
            int col = col_base + nt * 8;
            float b0 = bias[col], b1 = bias[col + 1];
            int r0 = row_base + mt * 16;
            *(float2*)(C + (size_t)r0 * N + col) =
                make_float2(acc[mt][nt][0] + b0, acc[mt][nt][1] + b1);
            *(float2*)(C + (size_t)(r0 + 8) * N + col) =
                make_float2(acc[mt][nt][2] + b0, acc[mt][nt][3] + b1);
        }
    }
}

// ---------------------------------------------------------------------------
// Flash attention, fp16 mixed precision (unchanged from R11 winner):
//   QK: (Qhi + Qlo) x Khi  (2 passes);  PV: (Phi + Plo) x Vhi  (2 passes)
// CTA: 64 q-rows x one (b,h), 128 threads, 3 CTAs/SM.
// ---------------------------------------------------------------------------
#define ATHREADS   128
#define KV_TILE_B  (64 * 128)              // 8192 (swizzled)
#define KV_STAGE_B (2 * KV_TILE_B)         // 16384 (Kh + Vh only)
#define ATTN_SMEM  (2 * KV_STAGE_B)        // 32768

__device__ __forceinline__ void attn_load_kv(
    const __half* Kh, const __half* Vh, int kc, uint32_t stg, int tid)
{
#pragma unroll
    for (int t = 0; t < 8; t++) {
        int f = tid + t * ATHREADS;        // 0..1023
        int tile = f >> 9;
        int idx  = f & 511;
        int row  = idx >> 3;
        int g    = idx & 7;
        const __half* src = (tile ? Vh : Kh) + (size_t)(kc + row) * HDIM + g * 8;
        uint32_t dst = stg + tile * KV_TILE_B + swz128(row, g);
        CP_ASYNC16(dst, (const void*)src);
    }
}

__global__ void __launch_bounds__(ATHREADS, 3)
attn_mma(const __half* __restrict__ hd_hi, const __half* __restrict__ hd_lo,
         __half* __restrict__ out_hi, __half* __restrict__ out_lo)
{
    extern __shared__ __align__(128) unsigned char smem_raw[];
    const uint32_t smem_base = smem_to_u32(smem_raw);
    const int tid  = threadIdx.x;
    const int w    = tid >> 5;             // 0..3
    const int lane = tid & 31;
    const int bh   = blockIdx.y;
    const int q0   = (gridDim.x - 1 - blockIdx.x) * 64;   // longest CTAs first
    const int b    = bh >> 4;
    const int h    = bh & 15;

    const size_t headelems = (size_t)SEQ * HDIM;
    const __half* Qh = hd_hi + (size_t)bh * headelems;
    const __half* Ql = hd_lo + (size_t)bh * headelems;
    const __half* Kh = hd_hi + (size_t)(BATCH * NHEADS + bh) * headelems;
    const __half* Vh = hd_hi + (size_t)(2 * BATCH * NHEADS + bh) * headelems;

    const uint32_t kvbase = smem_base;

    attn_load_kv(Kh, Vh, 0, kvbase, tid);
    CP_COMMIT();
    attn_load_kv(Kh, Vh, 64, kvbase + KV_STAGE_B, tid);
    CP_COMMIT();

    // Q fragments: gmem -> registers (A-frag lane mapping)
    uint32_t qh[4][4], ql[4][4];
    {
        const int r  = q0 + 16 * w + (lane >> 2);
        const int c  = 2 * (lane & 3);
        const __half* q0p = Qh + (size_t)r * HDIM + c;
        const __half* q1p = Ql + (size_t)r * HDIM + c;
#pragma unroll
        for (int s = 0; s < 4; s++) {
            qh[s][0] = *(const uint32_t*)(q0p + 16 * s);
            qh[s][1] = *(const uint32_t*)(q0p + 8 * HDIM + 16 * s);
            qh[s][2] = *(const uint32_t*)(q0p + 16 * s + 8);
            qh[s][3] = *(const uint32_t*)(q0p + 8 * HDIM + 16 * s + 8);
            ql[s][0] = *(const uint32_t*)(q1p + 16 * s);
            ql[s][1] = *(const uint32_t*)(q1p + 8 * HDIM + 16 * s);
            ql[s][2] = *(const uint32_t*)(q1p + 16 * s + 8);
            ql[s][3] = *(const uint32_t*)(q1p + 8 * HDIM + 16 * s + 8);
        }
    }

    const int nch = q0 / 64 + 1;

    float o[8][4];
#pragma unroll
    for (int j = 0; j < 8; j++)
#pragma unroll
        for (int e = 0; e < 4; e++) o[j][e] = 0.f;
    float m0r = -1e30f, m1r = -1e30f, l0r = 0.f, l1r = 0.f;

    const int g0 = q0 + 16 * w + (lane >> 2);
    const int g1 = g0 + 8;
    const int cb = 2 * (lane & 3);
    const int krow  = ((lane >> 4) * 8) + (lane & 7);
    const int kg    = (lane >> 3) & 1;
    const int vrow  = lane & 15;
    const int vg    = lane >> 4;

    for (int c = 0; c < nch; c++) {
        CP_WAIT(1);
        __syncthreads();

        const int kc = c * 64;
        const bool active = (kc <= q0 + 16 * w + 15);
        if (active) {
            const uint32_t stg = kvbase + (c & 1) * KV_STAGE_B;
            const uint32_t sKh = stg;
            const uint32_t sVh = stg + KV_TILE_B;

            float sfr[8][4];
#pragma unroll
            for (int j = 0; j < 8; j++)
#pragma unroll
                for (int e = 0; e < 4; e++) sfr[j][e] = 0.f;

#pragma unroll
            for (int s = 0; s < 4; s++) {
#pragma unroll
                for (int p = 0; p < 4; p++) {
                    uint32_t h0, h1, h2, h3;
                    ldsm_x4(sKh + swz128(16 * p + krow, 2 * s + kg), h0, h1, h2, h3);
                    uint32_t bh0[2] = {h0, h1}, bh1[2] = {h2, h3};
                    mma_f16(sfr[2 * p],     qh[s], bh0);
                    mma_f16(sfr[2 * p],     ql[s], bh0);
                    mma_f16(sfr[2 * p + 1], qh[s], bh1);
                    mma_f16(sfr[2 * p + 1], ql[s], bh1);
                }
            }

#pragma unroll
            for (int j = 0; j < 8; j++) {
                sfr[j][0] *= 0.125f; sfr[j][1] *= 0.125f;
                sfr[j][2] *= 0.125f; sfr[j][3] *= 0.125f;
            }
            if (kc + 63 > g0) {
#pragma unroll
                for (int j = 0; j < 8; j++) {
                    int col = kc + 8 * j + cb;
                    if (col     > g0) sfr[j][0] = -1e30f;
                    if (col + 1 > g0) sfr[j][1] = -1e30f;
                    if (col     > g1) sfr[j][2] = -1e30f;
                    if (col + 1 > g1) sfr[j][3] = -1e30f;
                }
            }

            float mx0 = -1e30f, mx1 = -1e30f;
#pragma unroll
            for (int j = 0; j < 8; j++) {
                mx0 = fmaxf(mx0, fmaxf(sfr[j][0], sfr[j][1]));
                mx1 = fmaxf(mx1, fmaxf(sfr[j][2], sfr[j][3]));
            }
            mx0 = fmaxf(mx0, __shfl_xor_sync(0xffffffffu, mx0, 1));
            mx0 = fmaxf(mx0, __shfl_xor_sync(0xffffffffu, mx0, 2));
            mx1 = fmaxf(mx1, __shfl_xor_sync(0xffffffffu, mx1, 1));
            mx1 = fmaxf(mx1, __shfl_xor_sync(0xffffffffu, mx1, 2));

            float mn0 = fmaxf(m0r, mx0), mn1 = fmaxf(m1r, mx1);
            float cr0 = __expf(m0r - mn0), cr1 = __expf(m1r - mn1);
            float sum0 = 0.f, sum1 = 0.f;
#pragma unroll
            for (int j = 0; j < 8; j++) {
                sfr[j][0] = __expf(sfr[j][0] - mn0);
                sfr[j][1] = __expf(sfr[j][1] - mn0);
                sfr[j][2] = __expf(sfr[j][2] - mn1);
                sfr[j][3] = __expf(sfr[j][3] - mn1);
                sum0 += sfr[j][0] + sfr[j][1];
                sum1 += sfr[j][2] + sfr[j][3];
            }
            sum0 += __shfl_xor_sync(0xffffffffu, sum0, 1);
            sum0 += __shfl_xor_sync(0xffffffffu, sum0, 2);
            sum1 += __shfl_xor_sync(0xffffffffu, sum1, 1);
            sum1 += __shfl_xor_sync(0xffffffffu, sum1, 2);

            l0r = l0r * cr0 + sum0;
            l1r = l1r * cr1 + sum1;
            m0r = mn0; m1r = mn1;
#pragma unroll
            for (int j = 0; j < 8; j++) {
                o[j][0] *= cr0; o[j][1] *= cr0;
                o[j][2] *= cr1; o[j][3] *= cr1;
            }

#pragma unroll
            for (int t = 0; t < 4; t++) {
                uint32_t ph[4], pl[4];
                {
                    const float* s0p = sfr[2 * t];
                    const float* s1p = sfr[2 * t + 1];
                    float v[8] = {s0p[0], s0p[1], s0p[2], s0p[3],
                                  s1p[0], s1p[1], s1p[2], s1p[3]};
#pragma unroll
                    for (int q = 0; q < 4; q++) {
                        uint32_t hp = pack_h2(v[2 * q], v[2 * q + 1]);
                        __half2 hv = *(__half2*)&hp;
                        float lo0 = v[2 * q]     - __half2float(hv.x);
                        float lo1 = v[2 * q + 1] - __half2float(hv.y);
                        ph[q] = hp;
                        pl[q] = pack_h2(lo0, lo1);
                    }
                }
#pragma unroll
                for (int d = 0; d < 4; d++) {
                    uint32_t v0, v1, v2, v3;
                    ldsm_x4_t(sVh + swz128(16 * t + vrow, 2 * d + vg), v0, v1, v2, v3);
                    uint32_t bh0[2] = {v0, v1}, bh1[2] = {v2, v3};
                    mma_f16(o[2 * d],     ph, bh0);
                    mma_f16(o[2 * d],     pl, bh0);
                    mma_f16(o[2 * d + 1], ph, bh1);
                    mma_f16(o[2 * d + 1], pl, bh1);
                }
            }
        }
        __syncthreads();
        if (c + 2 < nch)
            attn_load_kv(Kh, Vh, (c + 2) * 64, kvbase + (c & 1) * KV_STAGE_B, tid);
        CP_COMMIT();
    }
    CP_WAIT(0);

    const float i0 = 1.0f / l0r, i1 = 1.0f / l1r;
    const size_t base0 = ((size_t)(b * SEQ + g0)) * DMODEL + h * HDIM + cb;
    const size_t base1 = ((size_t)(b * SEQ + g1)) * DMODEL + h * HDIM + cb;
#pragma unroll
    for (int j = 0; j < 8; j++) {
        float x0 = o[j][0] * i0, x1 = o[j][1] * i0;
        float y0 = o[j][2] * i1, y1 = o[j][3] * i1;
        uint32_t hp0 = pack_h2(x0, x1);
        __half2 hv0 = *(__half2*)&hp0;
        uint32_t lp0 = pack_h2(x0 - __half2float(hv0.x), x1 - __half2float(hv0.y));
        uint32_t hp1 = pack_h2(y0, y1);
        __half2 hv1 = *(__half2*)&hp1;
        uint32_t lp1 = pack_h2(y0 - __half2float(hv1.x), y1 - __half2float(hv1.y));
        *(uint32_t*)(out_hi + base0 + 8 * j) = hp0;
        *(uint32_t*)(out_lo + base0 + 8 * j) = lp0;
        *(uint32_t*)(out_hi + base1 + 8 * j) = hp1;
        *(uint32_t*)(out_lo + base1 + 8 * j) = lp1;
    }
}

// ---------------------------------------------------------------------------
// Launch
// ---------------------------------------------------------------------------
extern "C" void kernel_launch(void* const* d_in, const int* in_sizes, int n_in,
                              void* d_out, int out_size)
{
    const float* x     = (const float*)d_in[0];
    const float* w_qkv = (const float*)d_in[1];
    const float* b_qkv = (const float*)d_in[2];
    const float* w_out = (const float*)d_in[3];
    const float* b_out = (const float*)d_in[4];
    float* out = (float*)d_out;

    __half *x_hi, *x_lo, *wq_hi, *wo_hi;
    __half *hd_hi, *hd_lo, *at_hi, *at_lo;
    cudaGetSymbolAddress((void**)&x_hi,  g_x_hi);
    cudaGetSymbolAddress((void**)&x_lo,  g_x_lo);
    cudaGetSymbolAddress((void**)&wq_hi, g_wqkv_hi);
    cudaGetSymbolAddress((void**)&wo_hi, g_wout_hi);
    cudaGetSymbolAddress((void**)&hd_hi, g_hd_hi);
    cudaGetSymbolAddress((void**)&hd_lo, g_hd_lo);
    cudaGetSymbolAddress((void**)&at_hi, g_attn_hi);
    cudaGetSymbolAddress((void**)&at_lo, g_attn_lo);

    cudaFuncSetAttribute(gemm_qkv,
                         cudaFuncAttributeMaxDynamicSharedMemorySize, GEMM_SMEM);
    cudaFuncSetAttribute(gemm_splitf16,
                         cudaFuncAttributeMaxDynamicSharedMemorySize, GEMM_SMEM);
    cudaFuncSetAttribute(attn_mma,
                         cudaFuncAttributeMaxDynamicSharedMemorySize, ATTN_SMEM);

    // Unified splits (1 launch)
    {
        int total = NX4 + NQ4 + NO4;
        split_all_kernel<<<(total + 255) / 256, 256>>>(
            x, w_qkv, w_out, x_hi, x_lo, wq_hi, wo_hi);
    }

    // 1) QKV projection -> head-major q/k/v (hi; lo for Q only)
    {
        dim3 grid(QKVDIM / 128, TOKENS / 128);
        gemm_qkv<<<grid, 256, GEMM_SMEM>>>(x_hi, x_lo, wq_hi, b_qkv, hd_hi, hd_lo);
    }

    // 2) Flash attention (fp16, 2-pass QK + 2-pass PV) -> split attn output
    {
        dim3 grid(SEQ / 64, BATCH * NHEADS);
        attn_mma<<<grid, ATHREADS, ATTN_SMEM>>>(hd_hi, hd_lo, at_hi, at_lo);
    }

    // 3) Output projection
    {
        dim3 grid(DMODEL / 128, TOKENS / 128);
        gemm_splitf16<<<grid, 256, GEMM_SMEM>>>(
            at_hi, at_lo, wo_hi, b_out, out, TOKENS, DMODEL, DMODEL);
    }
}

// round 13
// speedup vs baseline: 2.2132x; 1.5476x over previous
#include <cuda_runtime.h>
#include <cuda_fp16.h>
#include <cstdint>

// Problem constants
#define BATCH   2
#define SEQ     2048
#define DMODEL  1024
#define NHEADS  16
#define HDIM    64
#define TOKENS  (BATCH * SEQ)          // 4096
#define QKVDIM  (3 * DMODEL)           // 3072

// ---------------------------------------------------------------------------
// Scratch (no cudaMalloc allowed) — pure fp16
// ---------------------------------------------------------------------------
__device__ __half g_x_h[(size_t)TOKENS * DMODEL];
__device__ __half g_wqkv_h[(size_t)QKVDIM * DMODEL];
__device__ __half g_wout_h[(size_t)DMODEL * DMODEL];
// head-major Q/K/V: [which(3)][B*H][S][64]
__device__ __half g_hd[(size_t)3 * TOKENS * DMODEL];
// attention output, token-major [T][D]
__device__ __half g_attn[(size_t)TOKENS * DMODEL];

// ---------------------------------------------------------------------------
// Helpers (base ISA only — ptxas target is sm_103 without 'a')
// ---------------------------------------------------------------------------
__device__ __forceinline__ uint32_t smem_to_u32(const void* p) {
    uint32_t a;
    asm("{ .reg .u64 t; cvta.to.shared.u64 t, %1; cvt.u32.u64 %0, t; }" : "=r"(a) : "l"(p));
    return a;
}

#define CP_ASYNC16(dst, src) \
    asm volatile("cp.async.cg.shared.global [%0], [%1], 16;" :: "r"(dst), "l"(src) : "memory")
#define CP_COMMIT() asm volatile("cp.async.commit_group;" ::: "memory")
#define CP_WAIT(n)  asm volatile("cp.async.wait_group %0;" :: "n"(n) : "memory")

__device__ __forceinline__ void ldsm_x4(uint32_t addr, uint32_t& r0, uint32_t& r1,
                                        uint32_t& r2, uint32_t& r3) {
    asm volatile("ldmatrix.sync.aligned.m8n8.x4.shared.b16 {%0,%1,%2,%3}, [%4];"
                 : "=r"(r0), "=r"(r1), "=r"(r2), "=r"(r3) : "r"(addr));
}
__device__ __forceinline__ void ldsm_x4_t(uint32_t addr, uint32_t& r0, uint32_t& r1,
                                          uint32_t& r2, uint32_t& r3) {
    asm volatile("ldmatrix.sync.aligned.m8n8.x4.trans.shared.b16 {%0,%1,%2,%3}, [%4];"
                 : "=r"(r0), "=r"(r1), "=r"(r2), "=r"(r3) : "r"(addr));
}

__device__ __forceinline__ void mma_f16(float* d, const uint32_t* a, const uint32_t* b) {
    asm volatile(
        "mma.sync.aligned.m16n8k16.row.col.f32.f16.f16.f32 "
        "{%0,%1,%2,%3}, {%4,%5,%6,%7}, {%8,%9}, {%0,%1,%2,%3};"
        : "+f"(d[0]), "+f"(d[1]), "+f"(d[2]), "+f"(d[3])
        : "r"(a[0]), "r"(a[1]), "r"(a[2]), "r"(a[3]), "r"(b[0]), "r"(b[1]));
}

__device__ __forceinline__ uint32_t pack_h2(float x, float y) {
    __half2 h = __floats2half2_rn(x, y);
    return *(uint32_t*)&h;
}

// XOR swizzles: conflict-free ldmatrix on 64B / 128B rows.
__device__ __forceinline__ uint32_t swz64(int row, int g) {
    return (uint32_t)(row * 64 + ((g ^ ((row >> 1) & 3)) << 4));
}
__device__ __forceinline__ uint32_t swz128(int row, int g) {
    return (uint32_t)(row * 128 + ((g ^ (row & 7)) << 4));
}

// ---------------------------------------------------------------------------
// Unified convert kernel: fp32 -> fp16 for x, w_qkv, w_out
// ---------------------------------------------------------------------------
#define NX4 (TOKENS * DMODEL / 4)     // 1048576
#define NQ4 (QKVDIM * DMODEL / 4)     // 786432
#define NO4 (DMODEL * DMODEL / 4)     // 262144

__global__ void __launch_bounds__(256)
convert_all_kernel(const float* __restrict__ x, const float* __restrict__ wq,
                   const float* __restrict__ wo,
                   __half* __restrict__ xh, __half* __restrict__ wqh,
                   __half* __restrict__ woh)
{
    int i = blockIdx.x * blockDim.x + threadIdx.x;
    const float* in; __half* hi; int j;
    if (i < NX4)                  { in = x;  hi = xh;  j = i; }
    else if (i < NX4 + NQ4)       { in = wq; hi = wqh; j = i - NX4; }
    else if (i < NX4 + NQ4 + NO4) { in = wo; hi = woh; j = i - NX4 - NQ4; }
    else return;

    float4 v = ((const float4*)in)[j];
    ((__half2*)hi)[2 * j]     = __floats2half2_rn(v.x, v.y);
    ((__half2*)hi)[2 * j + 1] = __floats2half2_rn(v.z, v.w);
}

// ---------------------------------------------------------------------------
// GEMM mainloop: C = Ah x Bh^T  (pure fp16, 1 pass, fp32 accum).
// 128x128 tile, BK=32, 3 stages of 2 tiles (16KB), 8 warps, 2 CTAs/SM.
// ---------------------------------------------------------------------------
#define BK 32
#define NSTAGE 3
#define TILE_B (128 * 64)                  // 8192 bytes per 128x32 fp16 tile
#define STAGE_B (2 * TILE_B)               // 16384 (A, B)
#define GEMM_SMEM (NSTAGE * STAGE_B)       // 49152

__device__ __forceinline__ void gemm_load_stage(
    const __half* __restrict__ Ah, const __half* __restrict__ Bh,
    int K, int m0, int n0, int k0, uint32_t sbase, int tid)
{
#pragma unroll
    for (int t = 0; t < 4; t++) {
        int f    = tid + t * 256;          // 0..1023
        int tile = f >> 9;                 // 0..1
        int idx  = f & 511;
        int row  = idx >> 2;
        int g    = idx & 3;
        const __half* src = tile ? (Bh + (size_t)(n0 + row) * K + k0 + g * 8)
                                 : (Ah + (size_t)(m0 + row) * K + k0 + g * 8);
        uint32_t dst = sbase + tile * TILE_B + swz64(row, g);
        CP_ASYNC16(dst, (const void*)src);
    }
}

#define GEMM_MAINLOOP(Ah, Bh, K) \
    float acc[4][4][4]; \
    _Pragma("unroll") for (int i = 0; i < 4; i++) \
    _Pragma("unroll") for (int j = 0; j < 4; j++) \
    _Pragma("unroll") for (int f = 0; f < 4; f++) acc[i][j][f] = 0.f; \
    gemm_load_stage(Ah, Bh, K, m0, n0, 0, smem_base, tid); \
    CP_COMMIT(); \
    gemm_load_stage(Ah, Bh, K, m0, n0, BK, smem_base + STAGE_B, tid); \
    CP_COMMIT(); \
    const int a_row_in_tile = wm * 64 + (lane & 15); \
    const int a_g           = lane >> 4; \
    const int b_row_in_tile = wn * 32 + ((lane >> 4) * 8) + (lane & 7); \
    const int b_g           = (lane >> 3) & 1; \
    const int nchunk = K / BK; \
    for (int i = 0; i < nchunk; i++) { \
        CP_WAIT(1); \
        __syncthreads(); \
        if (i + 2 < nchunk) \
            gemm_load_stage(Ah, Bh, K, m0, n0, (i + 2) * BK, \
                            smem_base + ((i + 2) % NSTAGE) * STAGE_B, tid); \
        CP_COMMIT(); \
        const uint32_t st = smem_base + (i % NSTAGE) * STAGE_B; \
        const uint32_t sA = st, sB = st + TILE_B; \
        _Pragma("unroll") \
        for (int s = 0; s < 2; s++) { \
            uint32_t bh[4][2]; \
            _Pragma("unroll") \
            for (int p = 0; p < 2; p++) { \
                uint32_t r0, r1, r2, r3; \
                ldsm_x4(sB + swz64(b_row_in_tile + p * 16, 2 * s + b_g), r0, r1, r2, r3); \
                bh[2 * p][0] = r0; bh[2 * p][1] = r1; bh[2 * p + 1][0] = r2; bh[2 * p + 1][1] = r3; \
            } \
            _Pragma("unroll") \
            for (int mt = 0; mt < 4; mt++) { \
                uint32_t ah[4]; \
                ldsm_x4(sA + swz64(a_row_in_tile + mt * 16, 2 * s + a_g), \
                        ah[0], ah[1], ah[2], ah[3]); \
                _Pragma("unroll") \
                for (int nt = 0; nt < 4; nt++) \
                    mma_f16(acc[mt][nt], ah, bh[nt]); \
            } \
        } \
    }

// ---------------------------------------------------------------------------
// QKV GEMM: writes head-major fp16 q/k/v
// ---------------------------------------------------------------------------
__global__ void __launch_bounds__(256, 2)
gemm_qkv(const __half* __restrict__ Ah, const __half* __restrict__ Bh,
         const float* __restrict__ bias, __half* __restrict__ hd)
{
    extern __shared__ __align__(128) unsigned char smem_raw[];
    const uint32_t smem_base = smem_to_u32(smem_raw);
    const int tid = threadIdx.x, wid = tid >> 5, lane = tid & 31;
    const int wm = wid >> 2, wn = wid & 3;
    const int m0 = blockIdx.y * 128, n0 = blockIdx.x * 128;
    const int K = DMODEL;

    GEMM_MAINLOOP(Ah, Bh, K)

    const int row_base = m0 + wm * 64 + (lane >> 2);
    const int col_base = n0 + wn * 32 + 2 * (lane & 3);
#pragma unroll
    for (int mt = 0; mt < 4; mt++) {
#pragma unroll
        for (int nt = 0; nt < 4; nt++) {
            int col = col_base + nt * 8;
            int which = col >> 10;
            int head  = (col >> 6) & 15;
            int dim   = col & 63;
            float b0 = bias[col], b1 = bias[col + 1];
#pragma unroll
            for (int rr = 0; rr < 2; rr++) {
                int row = row_base + mt * 16 + rr * 8;
                float v0 = acc[mt][nt][2 * rr + 0] + b0;
                float v1 = acc[mt][nt][2 * rr + 1] + b1;
                int bb = row >> 11, s = row & 2047;
                size_t addr = (((size_t)(which * (BATCH * NHEADS) + bb * NHEADS + head))
                               * SEQ + s) * HDIM + dim;
                *(uint32_t*)(hd + addr) = pack_h2(v0, v1);
            }
        }
    }
}

// ---------------------------------------------------------------------------
// Out-proj GEMM: fp32 output + bias
// ---------------------------------------------------------------------------
__global__ void __launch_bounds__(256, 2)
gemm_f16(const __half* __restrict__ Ah, const __half* __restrict__ Bh,
         const float* __restrict__ bias, float* __restrict__ C,
         int M, int N, int K)
{
    extern __shared__ __align__(128) unsigned char smem_raw[];
    const uint32_t smem_base = smem_to_u32(smem_raw);
    const int tid = threadIdx.x, wid = tid >> 5, lane = tid & 31;
    const int wm = wid >> 2, wn = wid & 3;
    const int m0 = blockIdx.y * 128, n0 = blockIdx.x * 128;

    GEMM_MAINLOOP(Ah, Bh, K)

    const int row_base = m0 + wm * 64 + (lane >> 2);
    const int col_base = n0 + wn * 32 + 2 * (lane & 3);
#pragma unroll
    for (int mt = 0; mt < 4; mt++) {
#pragma unroll
        for (int nt = 0; nt < 4; nt++) {
            int col = col_base + nt * 8;
            float b0 = bias[col], b1 = bias[col + 1];
            int r0 = row_base + mt * 16;
            *(float2*)(C + (size_t)r0 * N + col) =
                make_float2(acc[mt][nt][0] + b0, acc[mt][nt][1] + b1);
            *(float2*)(C + (size_t)(r0 + 8) * N + col) =
                make_float2(acc[mt][nt][2] + b0, acc[mt][nt][3] + b1);
        }
    }
}

// ---------------------------------------------------------------------------
// Flash attention, pure fp16 operands, fp32 accum/softmax:
//   QK: Qh x Kh (1 pass);  PV: Ph x Vh (1 pass)
// CTA: 64 q-rows x one (b,h), 128 threads, 4 CTAs/SM.
// ---------------------------------------------------------------------------
#define ATHREADS   128
#define KV_TILE_B  (64 * 128)              // 8192 (swizzled)
#define KV_STAGE_B (2 * KV_TILE_B)         // 16384 (K + V)
#define ATTN_SMEM  (2 * KV_STAGE_B)        // 32768

__device__ __forceinline__ void attn_load_kv(
    const __half* Kh, const __half* Vh, int kc, uint32_t stg, int tid)
{
#pragma unroll
    for (int t = 0; t < 8; t++) {
        int f = tid + t * ATHREADS;        // 0..1023
        int tile = f >> 9;
        int idx  = f & 511;
        int row  = idx >> 3;
        int g    = idx & 7;
        const __half* src = (tile ? Vh : Kh) + (size_t)(kc + row) * HDIM + g * 8;
        uint32_t dst = stg + tile * KV_TILE_B + swz128(row, g);
        CP_ASYNC16(dst, (const void*)src);
    }
}

__global__ void __launch_bounds__(ATHREADS, 4)
attn_mma(const __half* __restrict__ hd, __half* __restrict__ out)
{
    extern __shared__ __align__(128) unsigned char smem_raw[];
    const uint32_t smem_base = smem_to_u32(smem_raw);
    const int tid  = threadIdx.x;
    const int w    = tid >> 5;             // 0..3
    const int lane = tid & 31;
    const int bh   = blockIdx.y;
    const int q0   = (gridDim.x - 1 - blockIdx.x) * 64;   // longest CTAs first
    const int b    = bh >> 4;
    const int h    = bh & 15;

    const size_t headelems = (size_t)SEQ * HDIM;
    const __half* Qh = hd + (size_t)bh * headelems;
    const __half* Kh = hd + (size_t)(BATCH * NHEADS + bh) * headelems;
    const __half* Vh = hd + (size_t)(2 * BATCH * NHEADS + bh) * headelems;

    const uint32_t kvbase = smem_base;

    attn_load_kv(Kh, Vh, 0, kvbase, tid);
    CP_COMMIT();
    attn_load_kv(Kh, Vh, 64, kvbase + KV_STAGE_B, tid);
    CP_COMMIT();

    // Q fragments: gmem -> registers (A-frag lane mapping)
    uint32_t qh[4][4];
    {
        const int r  = q0 + 16 * w + (lane >> 2);
        const int c  = 2 * (lane & 3);
        const __half* qp = Qh + (size_t)r * HDIM + c;
#pragma unroll
        for (int s = 0; s < 4; s++) {
            qh[s][0] = *(const uint32_t*)(qp + 16 * s);
            qh[s][1] = *(const uint32_t*)(qp + 8 * HDIM + 16 * s);
            qh[s][2] = *(const uint32_t*)(qp + 16 * s + 8);
            qh[s][3] = *(const uint32_t*)(qp + 8 * HDIM + 16 * s + 8);
        }
    }

    const int nch = q0 / 64 + 1;

    float o[8][4];
#pragma unroll
    for (int j = 0; j < 8; j++)
#pragma unroll
        for (int e = 0; e < 4; e++) o[j][e] = 0.f;
    float m0r = -1e30f, m1r = -1e30f, l0r = 0.f, l1r = 0.f;

    const int g0 = q0 + 16 * w + (lane >> 2);
    const int g1 = g0 + 8;
    const int cb = 2 * (lane & 3);
    const int krow  = ((lane >> 4) * 8) + (lane & 7);
    const int kg    = (lane >> 3) & 1;
    const int vrow  = lane & 15;
    const int vg    = lane >> 4;

    for (int c = 0; c < nch; c++) {
        CP_WAIT(1);
        __syncthreads();

        const int kc = c * 64;
        const bool active = (kc <= q0 + 16 * w + 15);
        if (active) {
            const uint32_t stg = kvbase + (c & 1) * KV_STAGE_B;
            const uint32_t sKh = stg;
            const uint32_t sVh = stg + KV_TILE_B;

            float sfr[8][4];
#pragma unroll
            for (int j = 0; j < 8; j++)
#pragma unroll
                for (int e = 0; e < 4; e++) sfr[j][e] = 0.f;

#pragma unroll
            for (int s = 0; s < 4; s++) {
#pragma unroll
                for (int p = 0; p < 4; p++) {
                    uint32_t h0, h1, h2, h3;
                    ldsm_x4(sKh + swz128(16 * p + krow, 2 * s + kg), h0, h1, h2, h3);
                    uint32_t bh0[2] = {h0, h1}, bh1[2] = {h2, h3};
                    mma_f16(sfr[2 * p],     qh[s], bh0);
                    mma_f16(sfr[2 * p + 1], qh[s], bh1);
                }
            }

#pragma unroll
            for (int j = 0; j < 8; j++) {
                sfr[j][0] *= 0.125f; sfr[j][1] *= 0.125f;
                sfr[j][2] *= 0.125f; sfr[j][3] *= 0.125f;
            }
            if (kc + 63 > g0) {
#pragma unroll
                for (int j = 0; j < 8; j++) {
                    int col = kc + 8 * j + cb;
                    if (col     > g0) sfr[j][0] = -1e30f;
                    if (col + 1 > g0) sfr[j][1] = -1e30f;
                    if (col     > g1) sfr[j][2] = -1e30f;
                    if (col + 1 > g1) sfr[j][3] = -1e30f;
                }
            }

            float mx0 = -1e30f, mx1 = -1e30f;
#pragma unroll
            for (int j = 0; j < 8; j++) {
                mx0 = fmaxf(mx0, fmaxf(sfr[j][0], sfr[j][1]));
                mx1 = fmaxf(mx1, fmaxf(sfr[j][2], sfr[j][3]));
            }
            mx0 = fmaxf(mx0, __shfl_xor_sync(0xffffffffu, mx0, 1));
            mx0 = fmaxf(mx0, __shfl_xor_sync(0xffffffffu, mx0, 2));
            mx1 = fmaxf(mx1, __shfl_xor_sync(0xffffffffu, mx1, 1));
            mx1 = fmaxf(mx1, __shfl_xor_sync(0xffffffffu, mx1, 2));

            float mn0 = fmaxf(m0r, mx0), mn1 = fmaxf(m1r, mx1);
            float cr0 = __expf(m0r - mn0), cr1 = __expf(m1r - mn1);
            float sum0 = 0.f, sum1 = 0.f;
#pragma unroll
            for (int j = 0; j < 8; j++) {
                sfr[j][0] = __expf(sfr[j][0] - mn0);
                sfr[j][1] = __expf(sfr[j][1] - mn0);
                sfr[j][2] = __expf(sfr[j][2] - mn1);
                sfr[j][3] = __expf(sfr[j][3] - mn1);
                sum0 += sfr[j][0] + sfr[j][1];
                sum1 += sfr[j][2] + sfr[j][3];
            }
            sum0 += __shfl_xor_sync(0xffffffffu, sum0, 1);
            sum0 += __shfl_xor_sync(0xffffffffu, sum0, 2);
            sum1 += __shfl_xor_sync(0xffffffffu, sum1, 1);
            sum1 += __shfl_xor_sync(0xffffffffu, sum1, 2);

            l0r = l0r * cr0 + sum0;
            l1r = l1r * cr1 + sum1;
            m0r = mn0; m1r = mn1;
#pragma unroll
            for (int j = 0; j < 8; j++) {
                o[j][0] *= cr0; o[j][1] *= cr0;
                o[j][2] *= cr1; o[j][3] *= cr1;
            }

            // ---- O += Ph Vh (fused pack, 1 pass) ----
#pragma unroll
            for (int t = 0; t < 4; t++) {
                uint32_t ph[4];
                {
                    const float* s0p = sfr[2 * t];
                    const float* s1p = sfr[2 * t + 1];
                    ph[0] = pack_h2(s0p[0], s0p[1]);
                    ph[1] = pack_h2(s0p[2], s0p[3]);
                    ph[2] = pack_h2(s1p[0], s1p[1]);
                    ph[3] = pack_h2(s1p[2], s1p[3]);
                }
#pragma unroll
                for (int d = 0; d < 4; d++) {
                    uint32_t v0, v1, v2, v3;
                    ldsm_x4_t(sVh + swz128(16 * t + vrow, 2 * d + vg), v0, v1, v2, v3);
                    uint32_t bh0[2] = {v0, v1}, bh1[2] = {v2, v3};
                    mma_f16(o[2 * d],     ph, bh0);
                    mma_f16(o[2 * d + 1], ph, bh1);
                }
            }
        }
        __syncthreads();
        if (c + 2 < nch)
            attn_load_kv(Kh, Vh, (c + 2) * 64, kvbase + (c & 1) * KV_STAGE_B, tid);
        CP_COMMIT();
    }
    CP_WAIT(0);

    const float i0 = 1.0f / l0r, i1 = 1.0f / l1r;
    const size_t base0 = ((size_t)(b * SEQ + g0)) * DMODEL + h * HDIM + cb;
    const size_t base1 = ((size_t)(b * SEQ + g1)) * DMODEL + h * HDIM + cb;
#pragma unroll
    for (int j = 0; j < 8; j++) {
        *(uint32_t*)(out + base0 + 8 * j) = pack_h2(o[j][0] * i0, o[j][1] * i0);
        *(uint32_t*)(out + base1 + 8 * j) = pack_h2(o[j][2] * i1, o[j][3] * i1);
    }
}

// ---------------------------------------------------------------------------
// Launch
// ---------------------------------------------------------------------------
extern "C" void kernel_launch(void* const* d_in, const int* in_sizes, int n_in,
                              void* d_out, int out_size)
{
    const float* x     = (const float*)d_in[0];
    const float* w_qkv = (const float*)d_in[1];
    const float* b_qkv = (const float*)d_in[2];
    const float* w_out = (const float*)d_in[3];
    const float* b_out = (const float*)d_in[4];
    float* out = (float*)d_out;

    __half *x_h, *wq_h, *wo_h, *hd, *at;
    cudaGetSymbolAddress((void**)&x_h,  g_x_h);
    cudaGetSymbolAddress((void**)&wq_h, g_wqkv_h);
    cudaGetSymbolAddress((void**)&wo_h, g_wout_h);
    cudaGetSymbolAddress((void**)&hd,   g_hd);
    cudaGetSymbolAddress((void**)&at,   g_attn);

    cudaFuncSetAttribute(gemm_qkv,
                         cudaFuncAttributeMaxDynamicSharedMemorySize, GEMM_SMEM);
    cudaFuncSetAttribute(gemm_f16,
                         cudaFuncAttributeMaxDynamicSharedMemorySize, GEMM_SMEM);
    cudaFuncSetAttribute(attn_mma,
                         cudaFuncAttributeMaxDynamicSharedMemorySize, ATTN_SMEM);

    // Converts (1 launch)
    {
        int total = NX4 + NQ4 + NO4;
        convert_all_kernel<<<(total + 255) / 256, 256>>>(
            x, w_qkv, w_out, x_h, wq_h, wo_h);
    }

    // 1) QKV projection -> head-major fp16 q/k/v
    {
        dim3 grid(QKVDIM / 128, TOKENS / 128);
        gemm_qkv<<<grid, 256, GEMM_SMEM>>>(x_h, wq_h, b_qkv, hd);
    }

    // 2) Flash attention (pure fp16 operands) -> fp16 attn output
    {
        dim3 grid(SEQ / 64, BATCH * NHEADS);
        attn_mma<<<grid, ATHREADS, ATTN_SMEM>>>(hd, at);
    }

    // 3) Output projection
    {
        dim3 grid(DMODEL / 128, TOKENS / 128);
        gemm_f16<<<grid, 256, GEMM_SMEM>>>(at, wo_h, b_out, out, TOKENS, DMODEL, DMODEL);
    }
}

// round 14
// speedup vs baseline: 2.3405x; 1.0575x over previous
#include <cuda_runtime.h>
#include <cuda_fp16.h>
#include <cstdint>

// Problem constants
#define BATCH   2
#define SEQ     2048
#define DMODEL  1024
#define NHEADS  16
#define HDIM    64
#define TOKENS  (BATCH * SEQ)          // 4096
#define QKVDIM  (3 * DMODEL)           // 3072

// ---------------------------------------------------------------------------
// Scratch (no cudaMalloc allowed) — pure fp16
// ---------------------------------------------------------------------------
__device__ __half g_x_h[(size_t)TOKENS * DMODEL];
__device__ __half g_wqkv_h[(size_t)QKVDIM * DMODEL];
__device__ __half g_wout_h[(size_t)DMODEL * DMODEL];
// head-major Q/K/V: [which(3)][B*H][S][64]
__device__ __half g_hd[(size_t)3 * TOKENS * DMODEL];
// attention output, token-major [T][D]
__device__ __half g_attn[(size_t)TOKENS * DMODEL];

// ---------------------------------------------------------------------------
// Helpers (base ISA only — ptxas target is sm_103 without 'a')
// ---------------------------------------------------------------------------
__device__ __forceinline__ uint32_t smem_to_u32(const void* p) {
    uint32_t a;
    asm("{ .reg .u64 t; cvta.to.shared.u64 t, %1; cvt.u32.u64 %0, t; }" : "=r"(a) : "l"(p));
    return a;
}

#define CP_ASYNC16(dst, src) \
    asm volatile("cp.async.cg.shared.global [%0], [%1], 16;" :: "r"(dst), "l"(src) : "memory")
#define CP_COMMIT() asm volatile("cp.async.commit_group;" ::: "memory")
#define CP_WAIT(n)  asm volatile("cp.async.wait_group %0;" :: "n"(n) : "memory")

__device__ __forceinline__ void ldsm_x4(uint32_t addr, uint32_t& r0, uint32_t& r1,
                                        uint32_t& r2, uint32_t& r3) {
    asm volatile("ldmatrix.sync.aligned.m8n8.x4.shared.b16 {%0,%1,%2,%3}, [%4];"
                 : "=r"(r0), "=r"(r1), "=r"(r2), "=r"(r3) : "r"(addr));
}
__device__ __forceinline__ void ldsm_x4_t(uint32_t addr, uint32_t& r0, uint32_t& r1,
                                          uint32_t& r2, uint32_t& r3) {
    asm volatile("ldmatrix.sync.aligned.m8n8.x4.trans.shared.b16 {%0,%1,%2,%3}, [%4];"
                 : "=r"(r0), "=r"(r1), "=r"(r2), "=r"(r3) : "r"(addr));
}

__device__ __forceinline__ void mma_f16(float* d, const uint32_t* a, const uint32_t* b) {
    asm volatile(
        "mma.sync.aligned.m16n8k16.row.col.f32.f16.f16.f32 "
        "{%0,%1,%2,%3}, {%4,%5,%6,%7}, {%8,%9}, {%0,%1,%2,%3};"
        : "+f"(d[0]), "+f"(d[1]), "+f"(d[2]), "+f"(d[3])
        : "r"(a[0]), "r"(a[1]), "r"(a[2]), "r"(a[3]), "r"(b[0]), "r"(b[1]));
}

__device__ __forceinline__ uint32_t pack_h2(float x, float y) {
    __half2 h = __floats2half2_rn(x, y);
    return *(uint32_t*)&h;
}

// XOR swizzle for 128-byte rows (8 granules of 16B): conflict-free ldmatrix.
__device__ __forceinline__ uint32_t swz128(int row, int g) {
    return (uint32_t)(row * 128 + ((g ^ (row & 7)) << 4));
}

// ---------------------------------------------------------------------------
// Unified convert kernel: fp32 -> fp16 for x, w_qkv, w_out
// ---------------------------------------------------------------------------
#define NX4 (TOKENS * DMODEL / 4)     // 1048576
#define NQ4 (QKVDIM * DMODEL / 4)     // 786432
#define NO4 (DMODEL * DMODEL / 4)     // 262144

__global__ void __launch_bounds__(256)
convert_all_kernel(const float* __restrict__ x, const float* __restrict__ wq,
                   const float* __restrict__ wo,
                   __half* __restrict__ xh, __half* __restrict__ wqh,
                   __half* __restrict__ woh)
{
    int i = blockIdx.x * blockDim.x + threadIdx.x;
    const float* in; __half* hi; int j;
    if (i < NX4)                  { in = x;  hi = xh;  j = i; }
    else if (i < NX4 + NQ4)       { in = wq; hi = wqh; j = i - NX4; }
    else if (i < NX4 + NQ4 + NO4) { in = wo; hi = woh; j = i - NX4 - NQ4; }
    else return;

    float4 v = ((const float4*)in)[j];
    ((__half2*)hi)[2 * j]     = __floats2half2_rn(v.x, v.y);
    ((__half2*)hi)[2 * j + 1] = __floats2half2_rn(v.z, v.w);
}

// ---------------------------------------------------------------------------
// GEMM mainloop: C = Ah x Bh^T  (pure fp16, fp32 accum).
// 128x128 tile, BK=64 (4 k16 steps per chunk), 3 stages of 2 tiles (32KB),
// 8 warps (2x4), 2 CTAs/SM. One barrier per 64-deep K chunk.
// ---------------------------------------------------------------------------
#define BK 64
#define NSTAGE 3
#define TILE_B (128 * 128)                 // 16384 bytes per 128x64 fp16 tile
#define STAGE_B (2 * TILE_B)               // 32768 (A, B)
#define GEMM_SMEM (NSTAGE * STAGE_B)       // 98304

__device__ __forceinline__ void gemm_load_stage(
    const __half* __restrict__ Ah, const __half* __restrict__ Bh,
    int K, int m0, int n0, int k0, uint32_t sbase, int tid)
{
#pragma unroll
    for (int t = 0; t < 8; t++) {
        int f    = tid + t * 256;          // 0..2047
        int tile = f >> 10;                // 0..1
        int idx  = f & 1023;
        int row  = idx >> 3;
        int g    = idx & 7;
        const __half* src = tile ? (Bh + (size_t)(n0 + row) * K + k0 + g * 8)
                                 : (Ah + (size_t)(m0 + row) * K + k0 + g * 8);
        uint32_t dst = sbase + tile * TILE_B + swz128(row, g);
        CP_ASYNC16(dst, (const void*)src);
    }
}

#define GEMM_MAINLOOP(Ah, Bh, K) \
    float acc[4][4][4]; \
    _Pragma("unroll") for (int i = 0; i < 4; i++) \
    _Pragma("unroll") for (int j = 0; j < 4; j++) \
    _Pragma("unroll") for (int f = 0; f < 4; f++) acc[i][j][f] = 0.f; \
    gemm_load_stage(Ah, Bh, K, m0, n0, 0, smem_base, tid); \
    CP_COMMIT(); \
    gemm_load_stage(Ah, Bh, K, m0, n0, BK, smem_base + STAGE_B, tid); \
    CP_COMMIT(); \
    const int a_row_in_tile = wm * 64 + (lane & 15); \
    const int a_g           = lane >> 4; \
    const int b_row_in_tile = wn * 32 + ((lane >> 4) * 8) + (lane & 7); \
    const int b_g           = (lane >> 3) & 1; \
    const int nchunk = K / BK; \
    for (int i = 0; i < nchunk; i++) { \
        CP_WAIT(1); \
        __syncthreads(); \
        if (i + 2 < nchunk) \
            gemm_load_stage(Ah, Bh, K, m0, n0, (i + 2) * BK, \
                            smem_base + ((i + 2) % NSTAGE) * STAGE_B, tid); \
        CP_COMMIT(); \
        const uint32_t st = smem_base + (i % NSTAGE) * STAGE_B; \
        const uint32_t sA = st, sB = st + TILE_B; \
        _Pragma("unroll") \
        for (int s = 0; s < 4; s++) { \
            uint32_t bh[4][2]; \
            _Pragma("unroll") \
            for (int p = 0; p < 2; p++) { \
                uint32_t r0, r1, r2, r3; \
                ldsm_x4(sB + swz128(b_row_in_tile + p * 16, 2 * s + b_g), r0, r1, r2, r3); \
                bh[2 * p][0] = r0; bh[2 * p][1] = r1; bh[2 * p + 1][0] = r2; bh[2 * p + 1][1] = r3; \
            } \
            _Pragma("unroll") \
            for (int mt = 0; mt < 4; mt++) { \
                uint32_t ah[4]; \
                ldsm_x4(sA + swz128(a_row_in_tile + mt * 16, 2 * s + a_g), \
                        ah[0], ah[1], ah[2], ah[3]); \
                _Pragma("unroll") \
                for (int nt = 0; nt < 4; nt++) \
                    mma_f16(acc[mt][nt], ah, bh[nt]); \
            } \
        } \
    }

// ---------------------------------------------------------------------------
// QKV GEMM: writes head-major fp16 q/k/v
// ---------------------------------------------------------------------------
__global__ void __launch_bounds__(256, 2)
gemm_qkv(const __half* __restrict__ Ah, const __half* __restrict__ Bh,
         const float* __restrict__ bias, __half* __restrict__ hd)
{
    extern __shared__ __align__(128) unsigned char smem_raw[];
    const uint32_t smem_base = smem_to_u32(smem_raw);
    const int tid = threadIdx.x, wid = tid >> 5, lane = tid & 31;
    const int wm = wid >> 2, wn = wid & 3;
    const int m0 = blockIdx.y * 128, n0 = blockIdx.x * 128;
    const int K = DMODEL;

    GEMM_MAINLOOP(Ah, Bh, K)

    const int row_base = m0 + wm * 64 + (lane >> 2);
    const int col_base = n0 + wn * 32 + 2 * (lane & 3);
#pragma unroll
    for (int mt = 0; mt < 4; mt++) {
#pragma unroll
        for (int nt = 0; nt < 4; nt++) {
            int col = col_base + nt * 8;
            int which = col >> 10;
            int head  = (col >> 6) & 15;
            int dim   = col & 63;
            float b0 = bias[col], b1 = bias[col + 1];
#pragma unroll
            for (int rr = 0; rr < 2; rr++) {
                int row = row_base + mt * 16 + rr * 8;
                float v0 = acc[mt][nt][2 * rr + 0] + b0;
                float v1 = acc[mt][nt][2 * rr + 1] + b1;
                int bb = row >> 11, s = row & 2047;
                size_t addr = (((size_t)(which * (BATCH * NHEADS) + bb * NHEADS + head))
                               * SEQ + s) * HDIM + dim;
                *(uint32_t*)(hd + addr) = pack_h2(v0, v1);
            }
        }
    }
}

// ---------------------------------------------------------------------------
// Out-proj GEMM: fp32 output + bias
// ---------------------------------------------------------------------------
__global__ void __launch_bounds__(256, 2)
gemm_f16(const __half* __restrict__ Ah, const __half* __restrict__ Bh,
         const float* __restrict__ bias, float* __restrict__ C,
         int M, int N, int K)
{
    extern __shared__ __align__(128) unsigned char smem_raw[];
    const uint32_t smem_base = smem_to_u32(smem_raw);
    const int tid = threadIdx.x, wid = tid >> 5, lane = tid & 31;
    const int wm = wid >> 2, wn = wid & 3;
    const int m0 = blockIdx.y * 128, n0 = blockIdx.x * 128;

    GEMM_MAINLOOP(Ah, Bh, K)

    const int row_base = m0 + wm * 64 + (lane >> 2);
    const int col_base = n0 + wn * 32 + 2 * (lane & 3);
#pragma unroll
    for (int mt = 0; mt < 4; mt++) {
#pragma unroll
        for (int nt = 0; nt < 4; nt++) {
            int col = col_base + nt * 8;
            float b0 = bias[col], b1 = bias[col + 1];
            int r0 = row_base + mt * 16;
            *(float2*)(C + (size_t)r0 * N + col) =
                make_float2(acc[mt][nt][0] + b0, acc[mt][nt][1] + b1);
            *(float2*)(C + (size_t)(r0 + 8) * N + col) =
                make_float2(acc[mt][nt][2] + b0, acc[mt][nt][3] + b1);
        }
    }
}

// ---------------------------------------------------------------------------
// Flash attention, pure fp16 operands, fp32 accum/softmax (R13 winner):
//   QK: Qh x Kh (1 pass);  PV: Ph x Vh (1 pass)
// CTA: 64 q-rows x one (b,h), 128 threads, 4 CTAs/SM.
// ---------------------------------------------------------------------------
#define ATHREADS   128
#define KV_TILE_B  (64 * 128)              // 8192 (swizzled)
#define KV_STAGE_B (2 * KV_TILE_B)         // 16384 (K + V)
#define ATTN_SMEM  (2 * KV_STAGE_B)        // 32768

__device__ __forceinline__ void attn_load_kv(
    const __half* Kh, const __half* Vh, int kc, uint32_t stg, int tid)
{
#pragma unroll
    for (int t = 0; t < 8; t++) {
        int f = tid + t * ATHREADS;        // 0..1023
        int tile = f >> 9;
        int idx  = f & 511;
        int row  = idx >> 3;
        int g    = idx & 7;
        const __half* src = (tile ? Vh : Kh) + (size_t)(kc + row) * HDIM + g * 8;
        uint32_t dst = stg + tile * KV_TILE_B + swz128(row, g);
        CP_ASYNC16(dst, (const void*)src);
    }
}

__global__ void __launch_bounds__(ATHREADS, 4)
attn_mma(const __half* __restrict__ hd, __half* __restrict__ out)
{
    extern __shared__ __align__(128) unsigned char smem_raw[];
    const uint32_t smem_base = smem_to_u32(smem_raw);
    const int tid  = threadIdx.x;
    const int w    = tid >> 5;             // 0..3
    const int lane = tid & 31;
    const int bh   = blockIdx.y;
    const int q0   = (gridDim.x - 1 - blockIdx.x) * 64;   // longest CTAs first
    const int b    = bh >> 4;
    const int h    = bh & 15;

    const size_t headelems = (size_t)SEQ * HDIM;
    const __half* Qh = hd + (size_t)bh * headelems;
    const __half* Kh = hd + (size_t)(BATCH * NHEADS + bh) * headelems;
    const __half* Vh = hd + (size_t)(2 * BATCH * NHEADS + bh) * headelems;

    const uint32_t kvbase = smem_base;

    attn_load_kv(Kh, Vh, 0, kvbase, tid);
    CP_COMMIT();
    attn_load_kv(Kh, Vh, 64, kvbase + KV_STAGE_B, tid);
    CP_COMMIT();

    // Q fragments: gmem -> registers (A-frag lane mapping)
    uint32_t qh[4][4];
    {
        const int r  = q0 + 16 * w + (lane >> 2);
        const int c  = 2 * (lane & 3);
        const __half* qp = Qh + (size_t)r * HDIM + c;
#pragma unroll
        for (int s = 0; s < 4; s++) {
            qh[s][0] = *(const uint32_t*)(qp + 16 * s);
            qh[s][1] = *(const uint32_t*)(qp + 8 * HDIM + 16 * s);
            qh[s][2] = *(const uint32_t*)(qp + 16 * s + 8);
            qh[s][3] = *(const uint32_t*)(qp + 8 * HDIM + 16 * s + 8);
        }
    }

    const int nch = q0 / 64 + 1;

    float o[8][4];
#pragma unroll
    for (int j = 0; j < 8; j++)
#pragma unroll
        for (int e = 0; e < 4; e++) o[j][e] = 0.f;
    float m0r = -1e30f, m1r = -1e30f, l0r = 0.f, l1r = 0.f;

    const int g0 = q0 + 16 * w + (lane >> 2);
    const int g1 = g0 + 8;
    const int cb = 2 * (lane & 3);
    const int krow  = ((lane >> 4) * 8) + (lane & 7);
    const int kg    = (lane >> 3) & 1;
    const int vrow  = lane & 15;
    const int vg    = lane >> 4;

    for (int c = 0; c < nch; c++) {
        CP_WAIT(1);
        __syncthreads();

        const int kc = c * 64;
        const bool active = (kc <= q0 + 16 * w + 15);
        if (active) {
            const uint32_t stg = kvbase + (c & 1) * KV_STAGE_B;
            const uint32_t sKh = stg;
            const uint32_t sVh = stg + KV_TILE_B;

            float sfr[8][4];
#pragma unroll
            for (int j = 0; j < 8; j++)
#pragma unroll
                for (int e = 0; e < 4; e++) sfr[j][e] = 0.f;

#pragma unroll
            for (int s = 0; s < 4; s++) {
#pragma unroll
                for (int p = 0; p < 4; p++) {
                    uint32_t h0, h1, h2, h3;
                    ldsm_x4(sKh + swz128(16 * p + krow, 2 * s + kg), h0, h1, h2, h3);
                    uint32_t bh0[2] = {h0, h1}, bh1[2] = {h2, h3};
                    mma_f16(sfr[2 * p],     qh[s], bh0);
                    mma_f16(sfr[2 * p + 1], qh[s], bh1);
                }
            }

#pragma unroll
            for (int j = 0; j < 8; j++) {
                sfr[j][0] *= 0.125f; sfr[j][1] *= 0.125f;
                sfr[j][2] *= 0.125f; sfr[j][3] *= 0.125f;
            }
            if (kc + 63 > g0) {
#pragma unroll
                for (int j = 0; j < 8; j++) {
                    int col = kc + 8 * j + cb;
                    if (col     > g0) sfr[j][0] = -1e30f;
                    if (col + 1 > g0) sfr[j][1] = -1e30f;
                    if (col     > g1) sfr[j][2] = -1e30f;
                    if (col + 1 > g1) sfr[j][3] = -1e30f;
                }
            }

            float mx0 = -1e30f, mx1 = -1e30f;
#pragma unroll
            for (int j = 0; j < 8; j++) {
                mx0 = fmaxf(mx0, fmaxf(sfr[j][0], sfr[j][1]));
                mx1 = fmaxf(mx1, fmaxf(sfr[j][2], sfr[j][3]));
            }
            mx0 = fmaxf(mx0, __shfl_xor_sync(0xffffffffu, mx0, 1));
            mx0 = fmaxf(mx0, __shfl_xor_sync(0xffffffffu, mx0, 2));
            mx1 = fmaxf(mx1, __shfl_xor_sync(0xffffffffu, mx1, 1));
            mx1 = fmaxf(mx1, __shfl_xor_sync(0xffffffffu, mx1, 2));

            float mn0 = fmaxf(m0r, mx0), mn1 = fmaxf(m1r, mx1);
            float cr0 = __expf(m0r - mn0), cr1 = __expf(m1r - mn1);
            float sum0 = 0.f, sum1 = 0.f;
#pragma unroll
            for (int j = 0; j < 8; j++) {
                sfr[j][0] = __expf(sfr[j][0] - mn0);
                sfr[j][1] = __expf(sfr[j][1] - mn0);
                sfr[j][2] = __expf(sfr[j][2] - mn1);
                sfr[j][3] = __expf(sfr[j][3] - mn1);
                sum0 += sfr[j][0] + sfr[j][1];
                sum1 += sfr[j][2] + sfr[j][3];
            }
            sum0 += __shfl_xor_sync(0xffffffffu, sum0, 1);
            sum0 += __shfl_xor_sync(0xffffffffu, sum0, 2);
            sum1 += __shfl_xor_sync(0xffffffffu, sum1, 1);
            sum1 += __shfl_xor_sync(0xffffffffu, sum1, 2);

            l0r = l0r * cr0 + sum0;
            l1r = l1r * cr1 + sum1;
            m0r = mn0; m1r = mn1;
#pragma unroll
            for (int j = 0; j < 8; j++) {
                o[j][0] *= cr0; o[j][1] *= cr0;
                o[j][2] *= cr1; o[j][3] *= cr1;
            }

            // ---- O += Ph Vh (fused pack, 1 pass) ----
#pragma unroll
            for (int t = 0; t < 4; t++) {
                uint32_t ph[4];
                {
                    const float* s0p = sfr[2 * t];
                    const float* s1p = sfr[2 * t + 1];
                    ph[0] = pack_h2(s0p[0], s0p[1]);
                    ph[1] = pack_h2(s0p[2], s0p[3]);
                    ph[2] = pack_h2(s1p[0], s1p[1]);
                    ph[3] = pack_h2(s1p[2], s1p[3]);
                }
#pragma unroll
                for (int d = 0; d < 4; d++) {
                    uint32_t v0, v1, v2, v3;
                    ldsm_x4_t(sVh + swz128(16 * t + vrow, 2 * d + vg), v0, v1, v2, v3);
                    uint32_t bh0[2] = {v0, v1}, bh1[2] = {v2, v3};
                    mma_f16(o[2 * d],     ph, bh0);
                    mma_f16(o[2 * d + 1], ph, bh1);
                }
            }
        }
        __syncthreads();
        if (c + 2 < nch)
            attn_load_kv(Kh, Vh, (c + 2) * 64, kvbase + (c & 1) * KV_STAGE_B, tid);
        CP_COMMIT();
    }
    CP_WAIT(0);

    const float i0 = 1.0f / l0r, i1 = 1.0f / l1r;
    const size_t base0 = ((size_t)(b * SEQ + g0)) * DMODEL + h * HDIM + cb;
    const size_t base1 = ((size_t)(b * SEQ + g1)) * DMODEL + h * HDIM + cb;
#pragma unroll
    for (int j = 0; j < 8; j++) {
        *(uint32_t*)(out + base0 + 8 * j) = pack_h2(o[j][0] * i0, o[j][1] * i0);
        *(uint32_t*)(out + base1 + 8 * j) = pack_h2(o[j][2] * i1, o[j][3] * i1);
    }
}

// ---------------------------------------------------------------------------
// Launch
// ---------------------------------------------------------------------------
extern "C" void kernel_launch(void* const* d_in, const int* in_sizes, int n_in,
                              void* d_out, int out_size)
{
    const float* x     = (const float*)d_in[0];
    const float* w_qkv = (const float*)d_in[1];
    const float* b_qkv = (const float*)d_in[2];
    const float* w_out = (const float*)d_in[3];
    const float* b_out = (const float*)d_in[4];
    float* out = (float*)d_out;

    __half *x_h, *wq_h, *wo_h, *hd, *at;
    cudaGetSymbolAddress((void**)&x_h,  g_x_h);
    cudaGetSymbolAddress((void**)&wq_h, g_wqkv_h);
    cudaGetSymbolAddress((void**)&wo_h, g_wout_h);
    cudaGetSymbolAddress((void**)&hd,   g_hd);
    cudaGetSymbolAddress((void**)&at,   g_attn);

    cudaFuncSetAttribute(gemm_qkv,
                         cudaFuncAttributeMaxDynamicSharedMemorySize, GEMM_SMEM);
    cudaFuncSetAttribute(gemm_f16,
                         cudaFuncAttributeMaxDynamicSharedMemorySize, GEMM_SMEM);
    cudaFuncSetAttribute(attn_mma,
                         cudaFuncAttributeMaxDynamicSharedMemorySize, ATTN_SMEM);

    // Converts (1 launch)
    {
        int total = NX4 + NQ4 + NO4;
        convert_all_kernel<<<(total + 255) / 256, 256>>>(
            x, w_qkv, w_out, x_h, wq_h, wo_h);
    }

    // 1) QKV projection -> head-major fp16 q/k/v
    {
        dim3 grid(QKVDIM / 128, TOKENS / 128);
        gemm_qkv<<<grid, 256, GEMM_SMEM>>>(x_h, wq_h, b_qkv, hd);
    }

    // 2) Flash attention (pure fp16 operands) -> fp16 attn output
    {
        dim3 grid(SEQ / 64, BATCH * NHEADS);
        attn_mma<<<grid, ATHREADS, ATTN_SMEM>>>(hd, at);
    }

    // 3) Output projection
    {
        dim3 grid(DMODEL / 128, TOKENS / 128);
        gemm_f16<<<grid, 256, GEMM_SMEM>>>(at, wo_h, b_out, out, TOKENS, DMODEL, DMODEL);
    }
}

// round 16
// speedup vs baseline: 2.4118x; 1.0305x over previous
#include <cuda_runtime.h>
#include <cuda_fp16.h>
#include <cstdint>

// Problem constants
#define BATCH   2
#define SEQ     2048
#define DMODEL  1024
#define NHEADS  16
#define HDIM    64
#define TOKENS  (BATCH * SEQ)          // 4096
#define QKVDIM  (3 * DMODEL)           // 3072

// ---------------------------------------------------------------------------
// Scratch (no cudaMalloc allowed) — pure fp16
// ---------------------------------------------------------------------------
__device__ __half g_x_h[(size_t)TOKENS * DMODEL];
__device__ __half g_wqkv_h[(size_t)QKVDIM * DMODEL];
__device__ __half g_wout_h[(size_t)DMODEL * DMODEL];
// head-major Q/K/V: [which(3)][B*H][S][64]
__device__ __half g_hd[(size_t)3 * TOKENS * DMODEL];
// attention output, token-major [T][D]
__device__ __half g_attn[(size_t)TOKENS * DMODEL];

// ---------------------------------------------------------------------------
// Helpers (base ISA only — ptxas target is sm_103 without 'a')
// ---------------------------------------------------------------------------
__device__ __forceinline__ uint32_t smem_to_u32(const void* p) {
    uint32_t a;
    asm("{ .reg .u64 t; cvta.to.shared.u64 t, %1; cvt.u32.u64 %0, t; }" : "=r"(a) : "l"(p));
    return a;
}

#define CP_ASYNC16(dst, src) \
    asm volatile("cp.async.cg.shared.global [%0], [%1], 16;" :: "r"(dst), "l"(src) : "memory")
#define CP_COMMIT() asm volatile("cp.async.commit_group;" ::: "memory")
#define CP_WAIT(n)  asm volatile("cp.async.wait_group %0;" :: "n"(n) : "memory")

__device__ __forceinline__ void ldsm_x4(uint32_t addr, uint32_t& r0, uint32_t& r1,
                                        uint32_t& r2, uint32_t& r3) {
    asm volatile("ldmatrix.sync.aligned.m8n8.x4.shared.b16 {%0,%1,%2,%3}, [%4];"
                 : "=r"(r0), "=r"(r1), "=r"(r2), "=r"(r3) : "r"(addr));
}
__device__ __forceinline__ void ldsm_x4_t(uint32_t addr, uint32_t& r0, uint32_t& r1,
                                          uint32_t& r2, uint32_t& r3) {
    asm volatile("ldmatrix.sync.aligned.m8n8.x4.trans.shared.b16 {%0,%1,%2,%3}, [%4];"
                 : "=r"(r0), "=r"(r1), "=r"(r2), "=r"(r3) : "r"(addr));
}

__device__ __forceinline__ void mma_f16(float* d, const uint32_t* a, const uint32_t* b) {
    asm volatile(
        "mma.sync.aligned.m16n8k16.row.col.f32.f16.f16.f32 "
        "{%0,%1,%2,%3}, {%4,%5,%6,%7}, {%8,%9}, {%0,%1,%2,%3};"
        : "+f"(d[0]), "+f"(d[1]), "+f"(d[2]), "+f"(d[3])
        : "r"(a[0]), "r"(a[1]), "r"(a[2]), "r"(a[3]), "r"(b[0]), "r"(b[1]));
}

__device__ __forceinline__ uint32_t pack_h2(float x, float y) {
    __half2 h = __floats2half2_rn(x, y);
    return *(uint32_t*)&h;
}

// ex2.approx: single MUFU.EX2 (device exp2)
__device__ __forceinline__ float ex2(float x) {
    float r;
    asm("ex2.approx.f32 %0, %1;" : "=f"(r) : "f"(x));
    return r;
}

// XOR swizzle for 128-byte rows (8 granules of 16B): conflict-free ldmatrix.
__device__ __forceinline__ uint32_t swz128(int row, int g) {
    return (uint32_t)(row * 128 + ((g ^ (row & 7)) << 4));
}

// ---------------------------------------------------------------------------
// Unified convert kernel: fp32 -> fp16 for x, w_qkv, w_out
// ---------------------------------------------------------------------------
#define NX4 (TOKENS * DMODEL / 4)     // 1048576
#define NQ4 (QKVDIM * DMODEL / 4)     // 786432
#define NO4 (DMODEL * DMODEL / 4)     // 262144

__global__ void __launch_bounds__(256)
convert_all_kernel(const float* __restrict__ x, const float* __restrict__ wq,
                   const float* __restrict__ wo,
                   __half* __restrict__ xh, __half* __restrict__ wqh,
                   __half* __restrict__ woh)
{
    int i = blockIdx.x * blockDim.x + threadIdx.x;
    const float* in; __half* hi; int j;
    if (i < NX4)                  { in = x;  hi = xh;  j = i; }
    else if (i < NX4 + NQ4)       { in = wq; hi = wqh; j = i - NX4; }
    else if (i < NX4 + NQ4 + NO4) { in = wo; hi = woh; j = i - NX4 - NQ4; }
    else return;

    float4 v = ((const float4*)in)[j];
    ((__half2*)hi)[2 * j]     = __floats2half2_rn(v.x, v.y);
    ((__half2*)hi)[2 * j + 1] = __floats2half2_rn(v.z, v.w);
}

// ---------------------------------------------------------------------------
// GEMM mainloop: C = Ah x Bh^T  (pure fp16, fp32 accum).
// 128x128 tile, BK=64, 3 stages of 2 tiles (32KB), 8 warps, 2 CTAs/SM.
// ---------------------------------------------------------------------------
#define BK 64
#define NSTAGE 3
#define TILE_B (128 * 128)                 // 16384 bytes per 128x64 fp16 tile
#define STAGE_B (2 * TILE_B)               // 32768 (A, B)
#define GEMM_SMEM (NSTAGE * STAGE_B)       // 98304

__device__ __forceinline__ void gemm_load_stage(
    const __half* __restrict__ Ah, const __half* __restrict__ Bh,
    int K, int m0, int n0, int k0, uint32_t sbase, int tid)
{
#pragma unroll
    for (int t = 0; t < 8; t++) {
        int f    = tid + t * 256;          // 0..2047
        int tile = f >> 10;                // 0..1
        int idx  = f & 1023;
        int row  = idx >> 3;
        int g    = idx & 7;
        const __half* src = tile ? (Bh + (size_t)(n0 + row) * K + k0 + g * 8)
                                 : (Ah + (size_t)(m0 + row) * K + k0 + g * 8);
        uint32_t dst = sbase + tile * TILE_B + swz128(row, g);
        CP_ASYNC16(dst, (const void*)src);
    }
}

#define GEMM_MAINLOOP(Ah, Bh, K) \
    float acc[4][4][4]; \
    _Pragma("unroll") for (int i = 0; i < 4; i++) \
    _Pragma("unroll") for (int j = 0; j < 4; j++) \
    _Pragma("unroll") for (int f = 0; f < 4; f++) acc[i][j][f] = 0.f; \
    gemm_load_stage(Ah, Bh, K, m0, n0, 0, smem_base, tid); \
    CP_COMMIT(); \
    gemm_load_stage(Ah, Bh, K, m0, n0, BK, smem_base + STAGE_B, tid); \
    CP_COMMIT(); \
    const int a_row_in_tile = wm * 64 + (lane & 15); \
    const int a_g           = lane >> 4; \
    const int b_row_in_tile = wn * 32 + ((lane >> 4) * 8) + (lane & 7); \
    const int b_g           = (lane >> 3) & 1; \
    const int nchunk = K / BK; \
    for (int i = 0; i < nchunk; i++) { \
        CP_WAIT(1); \
        __syncthreads(); \
        if (i + 2 < nchunk) \
            gemm_load_stage(Ah, Bh, K, m0, n0, (i + 2) * BK, \
                            smem_base + ((i + 2) % NSTAGE) * STAGE_B, tid); \
        CP_COMMIT(); \
        const uint32_t st = smem_base + (i % NSTAGE) * STAGE_B; \
        const uint32_t sA = st, sB = st + TILE_B; \
        _Pragma("unroll") \
        for (int s = 0; s < 4; s++) { \
            uint32_t bh[4][2]; \
            _Pragma("unroll") \
            for (int p = 0; p < 2; p++) { \
                uint32_t r0, r1, r2, r3; \
                ldsm_x4(sB + swz128(b_row_in_tile + p * 16, 2 * s + b_g), r0, r1, r2, r3); \
                bh[2 * p][0] = r0; bh[2 * p][1] = r1; bh[2 * p + 1][0] = r2; bh[2 * p + 1][1] = r3; \
            } \
            _Pragma("unroll") \
            for (int mt = 0; mt < 4; mt++) { \
                uint32_t ah[4]; \
                ldsm_x4(sA + swz128(a_row_in_tile + mt * 16, 2 * s + a_g), \
                        ah[0], ah[1], ah[2], ah[3]); \
                _Pragma("unroll") \
                for (int nt = 0; nt < 4; nt++) \
                    mma_f16(acc[mt][nt], ah, bh[nt]); \
            } \
        } \
    }

// ---------------------------------------------------------------------------
// QKV GEMM: writes head-major fp16 q/k/v
// ---------------------------------------------------------------------------
__global__ void __launch_bounds__(256, 2)
gemm_qkv(const __half* __restrict__ Ah, const __half* __restrict__ Bh,
         const float* __restrict__ bias, __half* __restrict__ hd)
{
    extern __shared__ __align__(128) unsigned char smem_raw[];
    const uint32_t smem_base = smem_to_u32(smem_raw);
    const int tid = threadIdx.x, wid = tid >> 5, lane = tid & 31;
    const int wm = wid >> 2, wn = wid & 3;
    const int m0 = blockIdx.y * 128, n0 = blockIdx.x * 128;
    const int K = DMODEL;

    GEMM_MAINLOOP(Ah, Bh, K)

    const int row_base = m0 + wm * 64 + (lane >> 2);
    const int col_base = n0 + wn * 32 + 2 * (lane & 3);
#pragma unroll
    for (int mt = 0; mt < 4; mt++) {
#pragma unroll
        for (int nt = 0; nt < 4; nt++) {
            int col = col_base + nt * 8;
            int which = col >> 10;
            int head  = (col >> 6) & 15;
            int dim   = col & 63;
            float b0 = bias[col], b1 = bias[col + 1];
#pragma unroll
            for (int rr = 0; rr < 2; rr++) {
                int row = row_base + mt * 16 + rr * 8;
                float v0 = acc[mt][nt][2 * rr + 0] + b0;
                float v1 = acc[mt][nt][2 * rr + 1] + b1;
                int bb = row >> 11, s = row & 2047;
                size_t addr = (((size_t)(which * (BATCH * NHEADS) + bb * NHEADS + head))
                               * SEQ + s) * HDIM + dim;
                *(uint32_t*)(hd + addr) = pack_h2(v0, v1);
            }
        }
    }
}

// ---------------------------------------------------------------------------
// Out-proj GEMM: fp32 output + bias
// ---------------------------------------------------------------------------
__global__ void __launch_bounds__(256, 2)
gemm_f16(const __half* __restrict__ Ah, const __half* __restrict__ Bh,
         const float* __restrict__ bias, float* __restrict__ C,
         int M, int N, int K)
{
    extern __shared__ __align__(128) unsigned char smem_raw[];
    const uint32_t smem_base = smem_to_u32(smem_raw);
    const int tid = threadIdx.x, wid = tid >> 5, lane = tid & 31;
    const int wm = wid >> 2, wn = wid & 3;
    const int m0 = blockIdx.y * 128, n0 = blockIdx.x * 128;

    GEMM_MAINLOOP(Ah, Bh, K)

    const int row_base = m0 + wm * 64 + (lane >> 2);
    const int col_base = n0 + wn * 32 + 2 * (lane & 3);
#pragma unroll
    for (int mt = 0; mt < 4; mt++) {
#pragma unroll
        for (int nt = 0; nt < 4; nt++) {
            int col = col_base + nt * 8;
            float b0 = bias[col], b1 = bias[col + 1];
            int r0 = row_base + mt * 16;
            *(float2*)(C + (size_t)r0 * N + col) =
                make_float2(acc[mt][nt][0] + b0, acc[mt][nt][1] + b1);
            *(float2*)(C + (size_t)(r0 + 8) * N + col) =
                make_float2(acc[mt][nt][2] + b0, acc[mt][nt][3] + b1);
        }
    }
}

// ---------------------------------------------------------------------------
// Flash attention, pure fp16 operands, fp32 accum, base-2 softmax (ex2.approx).
// CTA: 64 q-rows x one (b,h), 128 threads, 4 CTAs/SM.
// 3-stage KV pipeline, ONE barrier per chunk (cutlass-style).
// ---------------------------------------------------------------------------
#define ATHREADS   128
#define KV_TILE_B  (64 * 128)              // 8192 (swizzled)
#define KV_STAGE_B (2 * KV_TILE_B)         // 16384 (K + V)
#define KV_NSTAGE  3
#define ATTN_SMEM  (KV_NSTAGE * KV_STAGE_B)   // 49152
#define SCALE_LOG2E 0.1803368801f          // 0.125 * log2(e)

__device__ __forceinline__ void attn_load_kv(
    const __half* Kh, const __half* Vh, int kc, uint32_t stg, int tid)
{
#pragma unroll
    for (int t = 0; t < 8; t++) {
        int f = tid + t * ATHREADS;        // 0..1023
        int tile = f >> 9;
        int idx  = f & 511;
        int row  = idx >> 3;
        int g    = idx & 7;
        const __half* src = (tile ? Vh : Kh) + (size_t)(kc + row) * HDIM + g * 8;
        uint32_t dst = stg + tile * KV_TILE_B + swz128(row, g);
        CP_ASYNC16(dst, (const void*)src);
    }
}

__global__ void __launch_bounds__(ATHREADS, 4)
attn_mma(const __half* __restrict__ hd, __half* __restrict__ out)
{
    extern __shared__ __align__(128) unsigned char smem_raw[];
    const uint32_t smem_base = smem_to_u32(smem_raw);
    const int tid  = threadIdx.x;
    const int w    = tid >> 5;             // 0..3
    const int lane = tid & 31;
    const int bh   = blockIdx.y;
    const int q0   = (gridDim.x - 1 - blockIdx.x) * 64;   // longest CTAs first
    const int b    = bh >> 4;
    const int h    = bh & 15;

    const size_t headelems = (size_t)SEQ * HDIM;
    const __half* Qh = hd + (size_t)bh * headelems;
    const __half* Kh = hd + (size_t)(BATCH * NHEADS + bh) * headelems;
    const __half* Vh = hd + (size_t)(2 * BATCH * NHEADS + bh) * headelems;

    const uint32_t kvbase = smem_base;

    attn_load_kv(Kh, Vh, 0, kvbase, tid);
    CP_COMMIT();
    attn_load_kv(Kh, Vh, 64, kvbase + KV_STAGE_B, tid);
    CP_COMMIT();

    // Q fragments: gmem -> registers (A-frag lane mapping)
    uint32_t qh[4][4];
    {
        const int r  = q0 + 16 * w + (lane >> 2);
        const int c  = 2 * (lane & 3);
        const __half* qp = Qh + (size_t)r * HDIM + c;
#pragma unroll
        for (int s = 0; s < 4; s++) {
            qh[s][0] = *(const uint32_t*)(qp + 16 * s);
            qh[s][1] = *(const uint32_t*)(qp + 8 * HDIM + 16 * s);
            qh[s][2] = *(const uint32_t*)(qp + 16 * s + 8);
            qh[s][3] = *(const uint32_t*)(qp + 8 * HDIM + 16 * s + 8);
        }
    }

    const int nch = q0 / 64 + 1;

    float o[8][4];
#pragma unroll
    for (int j = 0; j < 8; j++)
#pragma unroll
        for (int e = 0; e < 4; e++) o[j][e] = 0.f;
    float m0r = -1e30f, m1r = -1e30f, l0r = 0.f, l1r = 0.f;

    const int g0 = q0 + 16 * w + (lane >> 2);
    const int g1 = g0 + 8;
    const int cb = 2 * (lane & 3);
    const int krow  = ((lane >> 4) * 8) + (lane & 7);
    const int kg    = (lane >> 3) & 1;
    const int vrow  = lane & 15;
    const int vg    = lane >> 4;

    for (int c = 0; c < nch; c++) {
        CP_WAIT(1);
        __syncthreads();
        // stage (c+2)%3 was last read at iteration c-1; all warps passed this
        // barrier only after finishing it -> safe to overwrite.
        if (c + 2 < nch)
            attn_load_kv(Kh, Vh, (c + 2) * 64,
                         kvbase + ((c + 2) % KV_NSTAGE) * KV_STAGE_B, tid);
        CP_COMMIT();

        const int kc = c * 64;
        const bool active = (kc <= q0 + 16 * w + 15);
        if (active) {
            const uint32_t stg = kvbase + (c % KV_NSTAGE) * KV_STAGE_B;
            const uint32_t sKh = stg;
            const uint32_t sVh = stg + KV_TILE_B;

            float sfr[8][4];
#pragma unroll
            for (int j = 0; j < 8; j++)
#pragma unroll
                for (int e = 0; e < 4; e++) sfr[j][e] = 0.f;

#pragma unroll
            for (int s = 0; s < 4; s++) {
#pragma unroll
                for (int p = 0; p < 4; p++) {
                    uint32_t h0, h1, h2, h3;
                    ldsm_x4(sKh + swz128(16 * p + krow, 2 * s + kg), h0, h1, h2, h3);
                    uint32_t bh0[2] = {h0, h1}, bh1[2] = {h2, h3};
                    mma_f16(sfr[2 * p],     qh[s], bh0);
                    mma_f16(sfr[2 * p + 1], qh[s], bh1);
                }
            }

            // scale into base-2 domain; causal mask
#pragma unroll
            for (int j = 0; j < 8; j++) {
                sfr[j][0] *= SCALE_LOG2E; sfr[j][1] *= SCALE_LOG2E;
                sfr[j][2] *= SCALE_LOG2E; sfr[j][3] *= SCALE_LOG2E;
            }
            if (kc + 63 > g0) {
#pragma unroll
                for (int j = 0; j < 8; j++) {
                    int col = kc + 8 * j + cb;
                    if (col     > g0) sfr[j][0] = -1e30f;
                    if (col + 1 > g0) sfr[j][1] = -1e30f;
                    if (col     > g1) sfr[j][2] = -1e30f;
                    if (col + 1 > g1) sfr[j][3] = -1e30f;
                }
            }

            float mx0 = -1e30f, mx1 = -1e30f;
#pragma unroll
            for (int j = 0; j < 8; j++) {
                mx0 = fmaxf(mx0, fmaxf(sfr[j][0], sfr[j][1]));
                mx1 = fmaxf(mx1, fmaxf(sfr[j][2], sfr[j][3]));
            }
            mx0 = fmaxf(mx0, __shfl_xor_sync(0xffffffffu, mx0, 1));
            mx0 = fmaxf(mx0, __shfl_xor_sync(0xffffffffu, mx0, 2));
            mx1 = fmaxf(mx1, __shfl_xor_sync(0xffffffffu, mx1, 1));
            mx1 = fmaxf(mx1, __shfl_xor_sync(0xffffffffu, mx1, 2));

            float mn0 = fmaxf(m0r, mx0), mn1 = fmaxf(m1r, mx1);
            float cr0 = ex2(m0r - mn0), cr1 = ex2(m1r - mn1);
            float sum0 = 0.f, sum1 = 0.f;
#pragma unroll
            for (int j = 0; j < 8; j++) {
                sfr[j][0] = ex2(sfr[j][0] - mn0);
                sfr[j][1] = ex2(sfr[j][1] - mn0);
                sfr[j][2] = ex2(sfr[j][2] - mn1);
                sfr[j][3] = ex2(sfr[j][3] - mn1);
                sum0 += sfr[j][0] + sfr[j][1];
                sum1 += sfr[j][2] + sfr[j][3];
            }
            sum0 += __shfl_xor_sync(0xffffffffu, sum0, 1);
            sum0 += __shfl_xor_sync(0xffffffffu, sum0, 2);
            sum1 += __shfl_xor_sync(0xffffffffu, sum1, 1);
            sum1 += __shfl_xor_sync(0xffffffffu, sum1, 2);

            l0r = l0r * cr0 + sum0;
            l1r = l1r * cr1 + sum1;
            m0r = mn0; m1r = mn1;
#pragma unroll
            for (int j = 0; j < 8; j++) {
                o[j][0] *= cr0; o[j][1] *= cr0;
                o[j][2] *= cr1; o[j][3] *= cr1;
            }

            // ---- O += Ph Vh (fused pack, 1 pass) ----
#pragma unroll
            for (int t = 0; t < 4; t++) {
                uint32_t ph[4];
                {
                    const float* s0p = sfr[2 * t];
                    const float* s1p = sfr[2 * t + 1];
                    ph[0] = pack_h2(s0p[0], s0p[1]);
                    ph[1] = pack_h2(s0p[2], s0p[3]);
                    ph[2] = pack_h2(s1p[0], s1p[1]);
                    ph[3] = pack_h2(s1p[2], s1p[3]);
                }
#pragma unroll
                for (int d = 0; d < 4; d++) {
                    uint32_t v0, v1, v2, v3;
                    ldsm_x4_t(sVh + swz128(16 * t + vrow, 2 * d + vg), v0, v1, v2, v3);
                    uint32_t bh0[2] = {v0, v1}, bh1[2] = {v2, v3};
                    mma_f16(o[2 * d],     ph, bh0);
                    mma_f16(o[2 * d + 1], ph, bh1);
                }
            }
        }
    }
    CP_WAIT(0);

    const float i0 = 1.0f / l0r, i1 = 1.0f / l1r;
    const size_t base0 = ((size_t)(b * SEQ + g0)) * DMODEL + h * HDIM + cb;
    const size_t base1 = ((size_t)(b * SEQ + g1)) * DMODEL + h * HDIM + cb;
#pragma unroll
    for (int j = 0; j < 8; j++) {
        *(uint32_t*)(out + base0 + 8 * j) = pack_h2(o[j][0] * i0, o[j][1] * i0);
        *(uint32_t*)(out + base1 + 8 * j) = pack_h2(o[j][2] * i1, o[j][3] * i1);
    }
}

// ---------------------------------------------------------------------------
// Launch
// ---------------------------------------------------------------------------
extern "C" void kernel_launch(void* const* d_in, const int* in_sizes, int n_in,
                              void* d_out, int out_size)
{
    const float* x     = (const float*)d_in[0];
    const float* w_qkv = (const float*)d_in[1];
    const float* b_qkv = (const float*)d_in[2];
    const float* w_out = (const float*)d_in[3];
    const float* b_out = (const float*)d_in[4];
    float* out = (float*)d_out;

    __half *x_h, *wq_h, *wo_h, *hd, *at;
    cudaGetSymbolAddress((void**)&x_h,  g_x_h);
    cudaGetSymbolAddress((void**)&wq_h, g_wqkv_h);
    cudaGetSymbolAddress((void**)&wo_h, g_wout_h);
    cudaGetSymbolAddress((void**)&hd,   g_hd);
    cudaGetSymbolAddress((void**)&at,   g_attn);

    cudaFuncSetAttribute(gemm_qkv,
                         cudaFuncAttributeMaxDynamicSharedMemorySize, GEMM_SMEM);
    cudaFuncSetAttribute(gemm_f16,
                         cudaFuncAttributeMaxDynamicSharedMemorySize, GEMM_SMEM);
    cudaFuncSetAttribute(attn_mma,
                         cudaFuncAttributeMaxDynamicSharedMemorySize, ATTN_SMEM);

    // Converts (1 launch)
    {
        int total = NX4 + NQ4 + NO4;
        convert_all_kernel<<<(total + 255) / 256, 256>>>(
            x, w_qkv, w_out, x_h, wq_h, wo_h);
    }

    // 1) QKV projection -> head-major fp16 q/k/v
    {
        dim3 grid(QKVDIM / 128, TOKENS / 128);
        gemm_qkv<<<grid, 256, GEMM_SMEM>>>(x_h, wq_h, b_qkv, hd);
    }

    // 2) Flash attention (3-stage KV, single barrier, base-2 softmax)
    {
        dim3 grid(SEQ / 64, BATCH * NHEADS);
        attn_mma<<<grid, ATHREADS, ATTN_SMEM>>>(hd, at);
    }

    // 3) Output projection
    {
        dim3 grid(DMODEL / 128, TOKENS / 128);
        gemm_f16<<<grid, 256, GEMM_SMEM>>>(at, wo_h, b_out, out, TOKENS, DMODEL, DMODEL);
    }
}

// round 17
// speedup vs baseline: 2.4225x; 1.0044x over previous
#include <cuda_runtime.h>
#include <cuda_fp16.h>
#include <cstdint>

// Problem constants
#define BATCH   2
#define SEQ     2048
#define DMODEL  1024
#define NHEADS  16
#define HDIM    64
#define TOKENS  (BATCH * SEQ)          // 4096
#define QKVDIM  (3 * DMODEL)           // 3072

// ---------------------------------------------------------------------------
// Scratch (no cudaMalloc allowed) — pure fp16
// ---------------------------------------------------------------------------
__device__ __half g_x_h[(size_t)TOKENS * DMODEL];
__device__ __half g_wqkv_h[(size_t)QKVDIM * DMODEL];
__device__ __half g_wout_h[(size_t)DMODEL * DMODEL];
// head-major Q/K/V: [which(3)][B*H][S][64]
__device__ __half g_hd[(size_t)3 * TOKENS * DMODEL];
// attention output, token-major [T][D]
__device__ __half g_attn[(size_t)TOKENS * DMODEL];

// ---------------------------------------------------------------------------
// Helpers (base ISA only — ptxas target is sm_103 without 'a')
// ---------------------------------------------------------------------------
__device__ __forceinline__ uint32_t smem_to_u32(const void* p) {
    uint32_t a;
    asm("{ .reg .u64 t; cvta.to.shared.u64 t, %1; cvt.u32.u64 %0, t; }" : "=r"(a) : "l"(p));
    return a;
}

#define CP_ASYNC16(dst, src) \
    asm volatile("cp.async.cg.shared.global [%0], [%1], 16;" :: "r"(dst), "l"(src) : "memory")
#define CP_COMMIT() asm volatile("cp.async.commit_group;" ::: "memory")
#define CP_WAIT(n)  asm volatile("cp.async.wait_group %0;" :: "n"(n) : "memory")

__device__ __forceinline__ void ldsm_x4(uint32_t addr, uint32_t& r0, uint32_t& r1,
                                        uint32_t& r2, uint32_t& r3) {
    asm volatile("ldmatrix.sync.aligned.m8n8.x4.shared.b16 {%0,%1,%2,%3}, [%4];"
                 : "=r"(r0), "=r"(r1), "=r"(r2), "=r"(r3) : "r"(addr));
}
__device__ __forceinline__ void ldsm_x4_t(uint32_t addr, uint32_t& r0, uint32_t& r1,
                                          uint32_t& r2, uint32_t& r3) {
    asm volatile("ldmatrix.sync.aligned.m8n8.x4.trans.shared.b16 {%0,%1,%2,%3}, [%4];"
                 : "=r"(r0), "=r"(r1), "=r"(r2), "=r"(r3) : "r"(addr));
}

__device__ __forceinline__ void mma_f16(float* d, const uint32_t* a, const uint32_t* b) {
    asm volatile(
        "mma.sync.aligned.m16n8k16.row.col.f32.f16.f16.f32 "
        "{%0,%1,%2,%3}, {%4,%5,%6,%7}, {%8,%9}, {%0,%1,%2,%3};"
        : "+f"(d[0]), "+f"(d[1]), "+f"(d[2]), "+f"(d[3])
        : "r"(a[0]), "r"(a[1]), "r"(a[2]), "r"(a[3]), "r"(b[0]), "r"(b[1]));
}

__device__ __forceinline__ uint32_t pack_h2(float x, float y) {
    __half2 h = __floats2half2_rn(x, y);
    return *(uint32_t*)&h;
}

// ex2.approx: single MUFU.EX2 (device exp2)
__device__ __forceinline__ float ex2(float x) {
    float r;
    asm("ex2.approx.f32 %0, %1;" : "=f"(r) : "f"(x));
    return r;
}

// XOR swizzle for 128-byte rows (8 granules of 16B): conflict-free ldmatrix.
__device__ __forceinline__ uint32_t swz128(int row, int g) {
    return (uint32_t)(row * 128 + ((g ^ (row & 7)) << 4));
}

// ---------------------------------------------------------------------------
// Unified convert kernel: fp32 -> fp16 for x, w_qkv, w_out
// ---------------------------------------------------------------------------
#define NX4 (TOKENS * DMODEL / 4)     // 1048576
#define NQ4 (QKVDIM * DMODEL / 4)     // 786432
#define NO4 (DMODEL * DMODEL / 4)     // 262144

__global__ void __launch_bounds__(256)
convert_all_kernel(const float* __restrict__ x, const float* __restrict__ wq,
                   const float* __restrict__ wo,
                   __half* __restrict__ xh, __half* __restrict__ wqh,
                   __half* __restrict__ woh)
{
    int i = blockIdx.x * blockDim.x + threadIdx.x;
    const float* in; __half* hi; int j;
    if (i < NX4)                  { in = x;  hi = xh;  j = i; }
    else if (i < NX4 + NQ4)       { in = wq; hi = wqh; j = i - NX4; }
    else if (i < NX4 + NQ4 + NO4) { in = wo; hi = woh; j = i - NX4 - NQ4; }
    else return;

    float4 v = ((const float4*)in)[j];
    ((__half2*)hi)[2 * j]     = __floats2half2_rn(v.x, v.y);
    ((__half2*)hi)[2 * j + 1] = __floats2half2_rn(v.z, v.w);
}

// ---------------------------------------------------------------------------
// GEMM: C = Ah x Bh^T  (pure fp16, fp32 accum).
// CTA: 128 threads (2x2 warps), tile 128x128, warp tile 64x64, BK=64.
// 3 stages of 2 tiles (32KB) = 96KB/CTA -> 2 CTAs/SM (8 warps, ~170 regs).
// Per k16 step/warp: 8 ldsm + 32 mma (ratio 4).
// ---------------------------------------------------------------------------
#define GTHREADS 128
#define BK 64
#define NSTAGE 3
#define TILE_B (128 * 128)                 // 16384 bytes per 128x64 fp16 tile
#define STAGE_B (2 * TILE_B)               // 32768 (A, B)
#define GEMM_SMEM (NSTAGE * STAGE_B)       // 98304

__device__ __forceinline__ void gemm_load_stage(
    const __half* __restrict__ Ah, const __half* __restrict__ Bh,
    int K, int m0, int n0, int k0, uint32_t sbase, int tid)
{
#pragma unroll
    for (int t = 0; t < 16; t++) {
        int f    = tid + t * GTHREADS;     // 0..2047
        int tile = f >> 10;                // 0..1
        int idx  = f & 1023;
        int row  = idx >> 3;
        int g    = idx & 7;
        const __half* src = tile ? (Bh + (size_t)(n0 + row) * K + k0 + g * 8)
                                 : (Ah + (size_t)(m0 + row) * K + k0 + g * 8);
        uint32_t dst = sbase + tile * TILE_B + swz128(row, g);
        CP_ASYNC16(dst, (const void*)src);
    }
}

#define GEMM_MAINLOOP(Ah, Bh, K) \
    float acc[4][8][4]; \
    _Pragma("unroll") for (int i = 0; i < 4; i++) \
    _Pragma("unroll") for (int j = 0; j < 8; j++) \
    _Pragma("unroll") for (int f = 0; f < 4; f++) acc[i][j][f] = 0.f; \
    gemm_load_stage(Ah, Bh, K, m0, n0, 0, smem_base, tid); \
    CP_COMMIT(); \
    gemm_load_stage(Ah, Bh, K, m0, n0, BK, smem_base + STAGE_B, tid); \
    CP_COMMIT(); \
    const int a_row_in_tile = wm * 64 + (lane & 15); \
    const int a_g           = lane >> 4; \
    const int b_row_in_tile = wn * 64 + ((lane >> 4) * 8) + (lane & 7); \
    const int b_g           = (lane >> 3) & 1; \
    const int nchunk = K / BK; \
    for (int i = 0; i < nchunk; i++) { \
        CP_WAIT(1); \
        __syncthreads(); \
        if (i + 2 < nchunk) \
            gemm_load_stage(Ah, Bh, K, m0, n0, (i + 2) * BK, \
                            smem_base + ((i + 2) % NSTAGE) * STAGE_B, tid); \
        CP_COMMIT(); \
        const uint32_t st = smem_base + (i % NSTAGE) * STAGE_B; \
        const uint32_t sA = st, sB = st + TILE_B; \
        _Pragma("unroll") \
        for (int s = 0; s < 4; s++) { \
            uint32_t bh[8][2]; \
            _Pragma("unroll") \
            for (int p = 0; p < 4; p++) { \
                uint32_t r0, r1, r2, r3; \
                ldsm_x4(sB + swz128(b_row_in_tile + p * 16, 2 * s + b_g), r0, r1, r2, r3); \
                bh[2 * p][0] = r0; bh[2 * p][1] = r1; bh[2 * p + 1][0] = r2; bh[2 * p + 1][1] = r3; \
            } \
            _Pragma("unroll") \
            for (int mt = 0; mt < 4; mt++) { \
                uint32_t ah[4]; \
                ldsm_x4(sA + swz128(a_row_in_tile + mt * 16, 2 * s + a_g), \
                        ah[0], ah[1], ah[2], ah[3]); \
                _Pragma("unroll") \
                for (int nt = 0; nt < 8; nt++) \
                    mma_f16(acc[mt][nt], ah, bh[nt]); \
            } \
        } \
    }

// ---------------------------------------------------------------------------
// QKV GEMM: writes head-major fp16 q/k/v
// ---------------------------------------------------------------------------
__global__ void __launch_bounds__(GTHREADS, 2)
gemm_qkv(const __half* __restrict__ Ah, const __half* __restrict__ Bh,
         const float* __restrict__ bias, __half* __restrict__ hd)
{
    extern __shared__ __align__(128) unsigned char smem_raw[];
    const uint32_t smem_base = smem_to_u32(smem_raw);
    const int tid = threadIdx.x, wid = tid >> 5, lane = tid & 31;
    const int wm = wid >> 1, wn = wid & 1;
    const int m0 = blockIdx.y * 128, n0 = blockIdx.x * 128;
    const int K = DMODEL;

    GEMM_MAINLOOP(Ah, Bh, K)

    const int row_base = m0 + wm * 64 + (lane >> 2);
    const int col_base = n0 + wn * 64 + 2 * (lane & 3);
#pragma unroll
    for (int mt = 0; mt < 4; mt++) {
#pragma unroll
        for (int nt = 0; nt < 8; nt++) {
            int col = col_base + nt * 8;
            int which = col >> 10;
            int head  = (col >> 6) & 15;
            int dim   = col & 63;
            float b0 = bias[col], b1 = bias[col + 1];
#pragma unroll
            for (int rr = 0; rr < 2; rr++) {
                int row = row_base + mt * 16 + rr * 8;
                float v0 = acc[mt][nt][2 * rr + 0] + b0;
                float v1 = acc[mt][nt][2 * rr + 1] + b1;
                int bb = row >> 11, s = row & 2047;
                size_t addr = (((size_t)(which * (BATCH * NHEADS) + bb * NHEADS + head))
                               * SEQ + s) * HDIM + dim;
                *(uint32_t*)(hd + addr) = pack_h2(v0, v1);
            }
        }
    }
}

// ---------------------------------------------------------------------------
// Out-proj GEMM: fp32 output + bias
// ---------------------------------------------------------------------------
__global__ void __launch_bounds__(GTHREADS, 2)
gemm_f16(const __half* __restrict__ Ah, const __half* __restrict__ Bh,
         const float* __restrict__ bias, float* __restrict__ C,
         int M, int N, int K)
{
    extern __shared__ __align__(128) unsigned char smem_raw[];
    const uint32_t smem_base = smem_to_u32(smem_raw);
    const int tid = threadIdx.x, wid = tid >> 5, lane = tid & 31;
    const int wm = wid >> 1, wn = wid & 1;
    const int m0 = blockIdx.y * 128, n0 = blockIdx.x * 128;

    GEMM_MAINLOOP(Ah, Bh, K)

    const int row_base = m0 + wm * 64 + (lane >> 2);
    const int col_base = n0 + wn * 64 + 2 * (lane & 3);
#pragma unroll
    for (int mt = 0; mt < 4; mt++) {
#pragma unroll
        for (int nt = 0; nt < 8; nt++) {
            int col = col_base + nt * 8;
            float b0 = bias[col], b1 = bias[col + 1];
            int r0 = row_base + mt * 16;
            *(float2*)(C + (size_t)r0 * N + col) =
                make_float2(acc[mt][nt][0] + b0, acc[mt][nt][1] + b1);
            *(float2*)(C + (size_t)(r0 + 8) * N + col) =
                make_float2(acc[mt][nt][2] + b0, acc[mt][nt][3] + b1);
        }
    }
}

// ---------------------------------------------------------------------------
// Flash attention, pure fp16 operands, fp32 accum, base-2 softmax (ex2.approx).
// CTA: 64 q-rows x one (b,h), 128 threads, 4 CTAs/SM.
// 3-stage KV pipeline, ONE barrier per chunk. (R16 winner, unchanged.)
// ---------------------------------------------------------------------------
#define ATHREADS   128
#define KV_TILE_B  (64 * 128)              // 8192 (swizzled)
#define KV_STAGE_B (2 * KV_TILE_B)         // 16384 (K + V)
#define KV_NSTAGE  3
#define ATTN_SMEM  (KV_NSTAGE * KV_STAGE_B)   // 49152
#define SCALE_LOG2E 0.1803368801f          // 0.125 * log2(e)

__device__ __forceinline__ void attn_load_kv(
    const __half* Kh, const __half* Vh, int kc, uint32_t stg, int tid)
{
#pragma unroll
    for (int t = 0; t < 8; t++) {
        int f = tid + t * ATHREADS;        // 0..1023
        int tile = f >> 9;
        int idx  = f & 511;
        int row  = idx >> 3;
        int g    = idx & 7;
        const __half* src = (tile ? Vh : Kh) + (size_t)(kc + row) * HDIM + g * 8;
        uint32_t dst = stg + tile * KV_TILE_B + swz128(row, g);
        CP_ASYNC16(dst, (const void*)src);
    }
}

__global__ void __launch_bounds__(ATHREADS, 4)
attn_mma(const __half* __restrict__ hd, __half* __restrict__ out)
{
    extern __shared__ __align__(128) unsigned char smem_raw[];
    const uint32_t smem_base = smem_to_u32(smem_raw);
    const int tid  = threadIdx.x;
    const int w    = tid >> 5;             // 0..3
    const int lane = tid & 31;
    const int bh   = blockIdx.y;
    const int q0   = (gridDim.x - 1 - blockIdx.x) * 64;   // longest CTAs first
    const int b    = bh >> 4;
    const int h    = bh & 15;

    const size_t headelems = (size_t)SEQ * HDIM;
    const __half* Qh = hd + (size_t)bh * headelems;
    const __half* Kh = hd + (size_t)(BATCH * NHEADS + bh) * headelems;
    const __half* Vh = hd + (size_t)(2 * BATCH * NHEADS + bh) * headelems;

    const uint32_t kvbase = smem_base;

    attn_load_kv(Kh, Vh, 0, kvbase, tid);
    CP_COMMIT();
    attn_load_kv(Kh, Vh, 64, kvbase + KV_STAGE_B, tid);
    CP_COMMIT();

    // Q fragments: gmem -> registers (A-frag lane mapping)
    uint32_t qh[4][4];
    {
        const int r  = q0 + 16 * w + (lane >> 2);
        const int c  = 2 * (lane & 3);
        const __half* qp = Qh + (size_t)r * HDIM + c;
#pragma unroll
        for (int s = 0; s < 4; s++) {
            qh[s][0] = *(const uint32_t*)(qp + 16 * s);
            qh[s][1] = *(const uint32_t*)(qp + 8 * HDIM + 16 * s);
            qh[s][2] = *(const uint32_t*)(qp + 16 * s + 8);
            qh[s][3] = *(const uint32_t*)(qp + 8 * HDIM + 16 * s + 8);
        }
    }

    const int nch = q0 / 64 + 1;

    float o[8][4];
#pragma unroll
    for (int j = 0; j < 8; j++)
#pragma unroll
        for (int e = 0; e < 4; e++) o[j][e] = 0.f;
    float m0r = -1e30f, m1r = -1e30f, l0r = 0.f, l1r = 0.f;

    const int g0 = q0 + 16 * w + (lane >> 2);
    const int g1 = g0 + 8;
    const int cb = 2 * (lane & 3);
    const int krow  = ((lane >> 4) * 8) + (lane & 7);
    const int kg    = (lane >> 3) & 1;
    const int vrow  = lane & 15;
    const int vg    = lane >> 4;

    for (int c = 0; c < nch; c++) {
        CP_WAIT(1);
        __syncthreads();
        // stage (c+2)%3 was last read at iteration c-1; all warps passed this
        // barrier only after finishing it -> safe to overwrite.
        if (c + 2 < nch)
            attn_load_kv(Kh, Vh, (c + 2) * 64,
                         kvbase + ((c + 2) % KV_NSTAGE) * KV_STAGE_B, tid);
        CP_COMMIT();

        const int kc = c * 64;
        const bool active = (kc <= q0 + 16 * w + 15);
        if (active) {
            const uint32_t stg = kvbase + (c % KV_NSTAGE) * KV_STAGE_B;
            const uint32_t sKh = stg;
            const uint32_t sVh = stg + KV_TILE_B;

            float sfr[8][4];
#pragma unroll
            for (int j = 0; j < 8; j++)
#pragma unroll
                for (int e = 0; e < 4; e++) sfr[j][e] = 0.f;

#pragma unroll
            for (int s = 0; s < 4; s++) {
#pragma unroll
                for (int p = 0; p < 4; p++) {
                    uint32_t h0, h1, h2, h3;
                    ldsm_x4(sKh + swz128(16 * p + krow, 2 * s + kg), h0, h1, h2, h3);
                    uint32_t bh0[2] = {h0, h1}, bh1[2] = {h2, h3};
                    mma_f16(sfr[2 * p],     qh[s], bh0);
                    mma_f16(sfr[2 * p + 1], qh[s], bh1);
                }
            }

            // scale into base-2 domain; causal mask
#pragma unroll
            for (int j = 0; j < 8; j++) {
                sfr[j][0] *= SCALE_LOG2E; sfr[j][1] *= SCALE_LOG2E;
                sfr[j][2] *= SCALE_LOG2E; sfr[j][3] *= SCALE_LOG2E;
            }
            if (kc + 63 > g0) {
#pragma unroll
                for (int j = 0; j < 8; j++) {
                    int col = kc + 8 * j + cb;
                    if (col     > g0) sfr[j][0] = -1e30f;
                    if (col + 1 > g0) sfr[j][1] = -1e30f;
                    if (col     > g1) sfr[j][2] = -1e30f;
                    if (col + 1 > g1) sfr[j][3] = -1e30f;
                }
            }

            float mx0 = -1e30f, mx1 = -1e30f;
#pragma unroll
            for (int j = 0; j < 8; j++) {
                mx0 = fmaxf(mx0, fmaxf(sfr[j][0], sfr[j][1]));
                mx1 = fmaxf(mx1, fmaxf(sfr[j][2], sfr[j][3]));
            }
            mx0 = fmaxf(mx0, __shfl_xor_sync(0xffffffffu, mx0, 1));
            mx0 = fmaxf(mx0, __shfl_xor_sync(0xffffffffu, mx0, 2));
            mx1 = fmaxf(mx1, __shfl_xor_sync(0xffffffffu, mx1, 1));
            mx1 = fmaxf(mx1, __shfl_xor_sync(0xffffffffu, mx1, 2));

            float mn0 = fmaxf(m0r, mx0), mn1 = fmaxf(m1r, mx1);
            float cr0 = ex2(m0r - mn0), cr1 = ex2(m1r - mn1);
            float sum0 = 0.f, sum1 = 0.f;
#pragma unroll
            for (int j = 0; j < 8; j++) {
                sfr[j][0] = ex2(sfr[j][0] - mn0);
                sfr[j][1] = ex2(sfr[j][1] - mn0);
                sfr[j][2] = ex2(sfr[j][2] - mn1);
                sfr[j][3] = ex2(sfr[j][3] - mn1);
                sum0 += sfr[j][0] + sfr[j][1];
                sum1 += sfr[j][2] + sfr[j][3];
            }
            sum0 += __shfl_xor_sync(0xffffffffu, sum0, 1);
            sum0 += __shfl_xor_sync(0xffffffffu, sum0, 2);
            sum1 += __shfl_xor_sync(0xffffffffu, sum1, 1);
            sum1 += __shfl_xor_sync(0xffffffffu, sum1, 2);

            l0r = l0r * cr0 + sum0;
            l1r = l1r * cr1 + sum1;
            m0r = mn0; m1r = mn1;
#pragma unroll
            for (int j = 0; j < 8; j++) {
                o[j][0] *= cr0; o[j][1] *= cr0;
                o[j][2] *= cr1; o[j][3] *= cr1;
            }

            // ---- O += Ph Vh (fused pack, 1 pass) ----
#pragma unroll
            for (int t = 0; t < 4; t++) {
                uint32_t ph[4];
                {
                    const float* s0p = sfr[2 * t];
                    const float* s1p = sfr[2 * t + 1];
                    ph[0] = pack_h2(s0p[0], s0p[1]);
                    ph[1] = pack_h2(s0p[2], s0p[3]);
                    ph[2] = pack_h2(s1p[0], s1p[1]);
                    ph[3] = pack_h2(s1p[2], s1p[3]);
                }
#pragma unroll
                for (int d = 0; d < 4; d++) {
                    uint32_t v0, v1, v2, v3;
                    ldsm_x4_t(sVh + swz128(16 * t + vrow, 2 * d + vg), v0, v1, v2, v3);
                    uint32_t bh0[2] = {v0, v1}, bh1[2] = {v2, v3};
                    mma_f16(o[2 * d],     ph, bh0);
                    mma_f16(o[2 * d + 1], ph, bh1);
                }
            }
        }
    }
    CP_WAIT(0);

    const float i0 = 1.0f / l0r, i1 = 1.0f / l1r;
    const size_t base0 = ((size_t)(b * SEQ + g0)) * DMODEL + h * HDIM + cb;
    const size_t base1 = ((size_t)(b * SEQ + g1)) * DMODEL + h * HDIM + cb;
#pragma unroll
    for (int j = 0; j < 8; j++) {
        *(uint32_t*)(out + base0 + 8 * j) = pack_h2(o[j][0] * i0, o[j][1] * i0);
        *(uint32_t*)(out + base1 + 8 * j) = pack_h2(o[j][2] * i1, o[j][3] * i1);
    }
}

// ---------------------------------------------------------------------------
// Launch
// ---------------------------------------------------------------------------
extern "C" void kernel_launch(void* const* d_in, const int* in_sizes, int n_in,
                              void* d_out, int out_size)
{
    const float* x     = (const float*)d_in[0];
    const float* w_qkv = (const float*)d_in[1];
    const float* b_qkv = (const float*)d_in[2];
    const float* w_out = (const float*)d_in[3];
    const float* b_out = (const float*)d_in[4];
    float* out = (float*)d_out;

    __half *x_h, *wq_h, *wo_h, *hd, *at;
    cudaGetSymbolAddress((void**)&x_h,  g_x_h);
    cudaGetSymbolAddress((void**)&wq_h, g_wqkv_h);
    cudaGetSymbolAddress((void**)&wo_h, g_wout_h);
    cudaGetSymbolAddress((void**)&hd,   g_hd);
    cudaGetSymbolAddress((void**)&at,   g_attn);

    cudaFuncSetAttribute(gemm_qkv,
                         cudaFuncAttributeMaxDynamicSharedMemorySize, GEMM_SMEM);
    cudaFuncSetAttribute(gemm_f16,
                         cudaFuncAttributeMaxDynamicSharedMemorySize, GEMM_SMEM);
    cudaFuncSetAttribute(attn_mma,
                         cudaFuncAttributeMaxDynamicSharedMemorySize, ATTN_SMEM);

    // Converts (1 launch)
    {
        int total = NX4 + NQ4 + NO4;
        convert_all_kernel<<<(total + 255) / 256, 256>>>(
            x, w_qkv, w_out, x_h, wq_h, wo_h);
    }

    // 1) QKV projection -> head-major fp16 q/k/v
    {
        dim3 grid(QKVDIM / 128, TOKENS / 128);
        gemm_qkv<<<grid, GTHREADS, GEMM_SMEM>>>(x_h, wq_h, b_qkv, hd);
    }

    // 2) Flash attention (3-stage KV, single barrier, base-2 softmax)
    {
        dim3 grid(SEQ / 64, BATCH * NHEADS);
        attn_mma<<<grid, ATHREADS, ATTN_SMEM>>>(hd, at);
    }

    // 3) Output projection
    {
        dim3 grid(DMODEL / 128, TOKENS / 128);
        gemm_f16<<<grid, GTHREADS, GEMM_SMEM>>>(at, wo_h, b_out, out, TOKENS, DMODEL, DMODEL);
    }
}